// round 2
// baseline (speedup 1.0000x reference)
#include <cuda_runtime.h>
#include <math.h>

#define N_RES   1024
#define DIM     256
#define NB      15
#define E_AB_LO 131072          // gathered edges
#define E_TOT   133120          // + 2*32*32 broadcast edges; = 4160 * 32
#define EPSF    1e-6f
#define TWO_PI  6.283185307179586f

#define TM      32              // edges per block in edge kernel
#define EDGE_BLOCKS (E_TOT / TM)   // 4160

// ---------------- device scratch (no runtime allocation allowed) ----------
__device__ float4 g_rep4[N_RES * (DIM / 4)];  // rep, float4-aligned for vector gathers
__device__ float  g_R[N_RES * 9];             // R[i*3+k] = e_{k}[i]  (columns are e1,e2,e3)
__device__ float  g_t[N_RES * 3];

// ---------------- helpers --------------------------------------------------
__device__ __forceinline__ float gelu_tanh(float x) {
    // jax.nn.gelu default: approximate=True (tanh form)
    float x3 = x * x * x;
    float inner = 0.7978845608028654f * (x + 0.044715f * x3);
    return 0.5f * x * (1.0f + tanhf(inner));
}

__device__ __forceinline__ unsigned long long pack2f(float lo, float hi) {
    unsigned long long r;
    asm("mov.b64 %0, {%1, %2};" : "=l"(r) : "f"(lo), "f"(hi));
    return r;
}
__device__ __forceinline__ void unpack2f(unsigned long long v, float& lo, float& hi) {
    asm("mov.b64 {%0, %1}, %2;" : "=f"(lo), "=f"(hi) : "l"(v));
}
__device__ __forceinline__ void ffma2(unsigned long long& d,
                                      unsigned long long a, unsigned long long b) {
    // packed f32x2 FMA: 2 fp32 FMAs per instruction on sm_103a
    asm("fma.rn.f32x2 %0, %1, %2, %0;" : "+l"(d) : "l"(a), "l"(b));
}

// ---------------- kernel 1: residue MLP (rep) ------------------------------
__global__ void residue_kernel(const float* __restrict__ emb,
                               const float* __restrict__ ts,
                               const float* __restrict__ tf,
                               const float* __restrict__ w1,
                               const float* __restrict__ b1,
                               const float* __restrict__ w2,
                               const float* __restrict__ b2) {
    __shared__ float sx[DIM + 32];
    __shared__ float sh[DIM];
    const int row = blockIdx.x;
    const int t   = threadIdx.x;

    sx[t] = emb[row * DIM + t];
    if (t < 32) {
        float x   = ts[row];
        float f   = tf[t & 15];
        float ang = TWO_PI * x * f;
        sx[DIM + t] = (t < 16) ? sinf(ang) : cosf(ang);
    }
    __syncthreads();

    float acc = b1[t];
    #pragma unroll 4
    for (int k = 0; k < DIM + 32; ++k) acc += sx[k] * w1[k * DIM + t];
    sh[t] = gelu_tanh(acc);
    __syncthreads();

    float acc2 = b2[t];
    #pragma unroll 4
    for (int k = 0; k < DIM; ++k) acc2 += sh[k] * w2[k * DIM + t];

    ((float*)g_rep4)[row * DIM + t] = acc2 + sx[t];   // + residual
}

// ---------------- kernel 2: rigid frames ------------------------------------
__global__ void frames_kernel(const float* __restrict__ coords) {
    int n = blockIdx.x * blockDim.x + threadIdx.x;
    if (n >= N_RES) return;
    const float* c = coords + n * 9;
    float ax = c[0], ay = c[1], az = c[2];
    float bx = c[3], by = c[4], bz = c[5];
    float cx = c[6], cy = c[7], cz = c[8];

    float v1x = cx - bx, v1y = cy - by, v1z = cz - bz;
    float v2x = ax - bx, v2y = ay - by, v2z = az - bz;

    float n1 = sqrtf(v1x * v1x + v1y * v1y + v1z * v1z) + EPSF;
    float e1x = v1x / n1, e1y = v1y / n1, e1z = v1z / n1;

    float dp  = e1x * v2x + e1y * v2y + e1z * v2z;
    float u2x = v2x - e1x * dp, u2y = v2y - e1y * dp, u2z = v2z - e1z * dp;
    float n2  = sqrtf(u2x * u2x + u2y * u2y + u2z * u2z) + EPSF;
    float e2x = u2x / n2, e2y = u2y / n2, e2z = u2z / n2;

    float e3x = e1y * e2z - e1z * e2y;
    float e3y = e1z * e2x - e1x * e2z;
    float e3z = e1x * e2y - e1y * e2x;

    float* R = g_R + n * 9;
    R[0] = e1x; R[1] = e2x; R[2] = e3x;
    R[3] = e1y; R[4] = e2y; R[5] = e3y;
    R[6] = e1z; R[7] = e2z; R[8] = e3z;
    g_t[n * 3 + 0] = bx; g_t[n * 3 + 1] = by; g_t[n * 3 + 2] = bz;
}

// ---------------- kernel 3: fused edge features + edge MLP ------------------
// smem layout (floats):
//   s_in  [TM][704]  edge_in tile
//   s_hid [TM][256]  gelu(edge_in @ w1 + b1)
//   s_gi  [TM][28]   27 geom features (padded)
//   s_disp[TM], s_scale[TM], s_src[TM], s_dst[TM]
#define S_IN_F   (TM * 704)
#define S_HID_F  (TM * 256)
#define S_GI_F   (TM * 28)
#define SMEM_EDGE_BYTES ((S_IN_F + S_HID_F + S_GI_F + TM * 2) * 4 + TM * 2 * 4)

__global__ void __launch_bounds__(256, 1)
edge_kernel(const float* __restrict__ w_geom,
            const float* __restrict__ chain_freq,
            const float* __restrict__ w1e,
            const float* __restrict__ b1e,
            const float* __restrict__ w2e,
            const float* __restrict__ b2e,
            const int* __restrict__ ri,
            const int* __restrict__ cid,
            const int* __restrict__ gA,
            const int* __restrict__ gB,
            const int* __restrict__ pid,
            float* __restrict__ out) {
    extern __shared__ float smem[];
    float* s_in    = smem;                       // TM x 704
    float* s_hid   = s_in + S_IN_F;              // TM x 256
    float* s_gi    = s_hid + S_HID_F;            // TM x 28
    float* s_disp  = s_gi + S_GI_F;
    float* s_scale = s_disp + TM;
    int*   s_src   = (int*)(s_scale + TM);
    int*   s_dst   = s_src + TM;

    const int t = threadIdx.x;

    // ---- Phase A1: per-edge scalars (32 threads) ----
    if (t < TM) {
        int e = blockIdx.x * TM + t;
        int src, dst;
        if (e < E_AB_LO) {
            src = gA[e];
            dst = gB[e];
        } else {
            int r = e - E_AB_LO;
            int bidx = r >> 10;        // / (32*32)
            int w    = r & 1023;
            src = pid[bidx * 32 + (w >> 5)];
            dst = pid[bidx * 32 + (w & 31)];
        }
        s_src[t] = src;
        s_dst[t] = dst;

        float disp = (float)(ri[src] - ri[dst]) * 0.125f;
        float m    = (cid[src] == cid[dst]) ? 1.0f : 0.0f;
        s_disp[t]  = disp;
        s_scale[t] = m / (fabsf(disp) + 1.0f);

        float Rs[9], Rd[9];
        #pragma unroll
        for (int i = 0; i < 9; ++i) { Rs[i] = g_R[src * 9 + i]; Rd[i] = g_R[dst * 9 + i]; }
        float dx = g_t[dst * 3 + 0] - g_t[src * 3 + 0];
        float dy = g_t[dst * 3 + 1] - g_t[src * 3 + 1];
        float dz = g_t[dst * 3 + 2] - g_t[src * 3 + 2];
        float dist = sqrtf(dx * dx + dy * dy + dz * dz + EPSF);

        float* gi = s_gi + t * 28;
        // rbf: centers linspace(0,20,15), sig = 20/15
        const float inv_sig = 15.0f / 20.0f;           // 0.75
        #pragma unroll
        for (int i = 0; i < NB; ++i) {
            float cc = (20.0f / 14.0f) * (float)i;
            float z  = (dist - cc) * inv_sig;
            gi[i] = expf(-0.5f * z * z);
        }
        // relrot[a*3+b] = sum_i Rs[i][a] * Rd[i][b]
        #pragma unroll
        for (int a = 0; a < 3; ++a)
            #pragma unroll
            for (int b = 0; b < 3; ++b)
                gi[15 + a * 3 + b] = Rs[0 + a] * Rd[0 + b] + Rs[3 + a] * Rd[3 + b] + Rs[6 + a] * Rd[6 + b];
        // local_k = (R_src^T d)_k / (dist + 1)
        float inv = 1.0f / (dist + 1.0f);
        #pragma unroll
        for (int k = 0; k < 3; ++k)
            gi[24 + k] = (Rs[k] * dx + Rs[3 + k] * dy + Rs[6 + k] * dz) * inv;
    }
    __syncthreads();

    const int eg = t >> 3;       // edge 0..31
    const int p  = t & 7;        // part 0..7

    // ---- Phase A2: geom = gi(27) @ w_geom(27x128) -> s_in[:,0:128] ----
    {
        float acc[16];
        #pragma unroll
        for (int q = 0; q < 16; ++q) acc[q] = 0.0f;
        const float* gi = s_gi + eg * 28;
        #pragma unroll
        for (int k = 0; k < 27; ++k) {
            float g = gi[k];
            const float* wg = w_geom + k * 128 + p * 16;
            #pragma unroll
            for (int q = 0; q < 16; ++q) acc[q] += g * wg[q];
        }
        float* drow = s_in + eg * 704;
        #pragma unroll
        for (int q = 0; q < 16; ++q) drow[p * 16 + q] = acc[q];
    }

    // ---- Phase A3: rope(64) -> s_in[:,128:192] ----
    {
        float disp = s_disp[eg];
        float sc   = s_scale[eg];
        float* drow = s_in + eg * 704 + 128;
        #pragma unroll
        for (int u = 0; u < 8; ++u) {
            int idx = p * 8 + u;
            float f   = chain_freq[idx & 31];
            float ang = TWO_PI * disp * f;
            drow[idx] = ((idx < 32) ? sinf(ang) : cosf(ang)) * sc;
        }
    }

    // ---- Phase A4: gather rep[src], rep[dst] -> s_in[:,192:704] ----
    {
        #pragma unroll
        for (int it = 0; it < 16; ++it) {
            int v    = t + it * 256;       // 0..4095 float4 chunks
            int e2   = v >> 7;
            int r    = v & 127;
            int half = r >> 6;
            int q    = r & 63;
            int idx  = half ? s_dst[e2] : s_src[e2];
            float4 val = g_rep4[idx * 64 + q];
            *(float4*)(s_in + e2 * 704 + 192 + half * 256 + q * 4) = val;
        }
    }
    __syncthreads();

    // ---- Phase B: GEMM1  hidden[32x256] = gelu(s_in @ w1e + b1e) ----
    const int lane = t & 31;
    const int mg   = t >> 5;     // 0..7 -> rows mg*4 .. mg*4+3
    {
        unsigned long long acc[4][4];
        #pragma unroll
        for (int m = 0; m < 4; ++m)
            #pragma unroll
            for (int q = 0; q < 4; ++q) acc[m][q] = 0ull;

        const float* a0 = s_in + (mg * 4 + 0) * 704;
        const float* a1 = s_in + (mg * 4 + 1) * 704;
        const float* a2 = s_in + (mg * 4 + 2) * 704;
        const float* a3 = s_in + (mg * 4 + 3) * 704;
        const char*  wp = (const char*)(w1e + lane * 8);

        #pragma unroll 4
        for (int k = 0; k < 704; ++k) {
            float av0 = a0[k], av1 = a1[k], av2 = a2[k], av3 = a3[k];
            ulonglong2 b01 = *(const ulonglong2*)(wp);
            ulonglong2 b23 = *(const ulonglong2*)(wp + 16);
            wp += 1024;
            unsigned long long A0 = pack2f(av0, av0);
            unsigned long long A1 = pack2f(av1, av1);
            unsigned long long A2 = pack2f(av2, av2);
            unsigned long long A3 = pack2f(av3, av3);
            ffma2(acc[0][0], A0, b01.x); ffma2(acc[0][1], A0, b01.y);
            ffma2(acc[0][2], A0, b23.x); ffma2(acc[0][3], A0, b23.y);
            ffma2(acc[1][0], A1, b01.x); ffma2(acc[1][1], A1, b01.y);
            ffma2(acc[1][2], A1, b23.x); ffma2(acc[1][3], A1, b23.y);
            ffma2(acc[2][0], A2, b01.x); ffma2(acc[2][1], A2, b01.y);
            ffma2(acc[2][2], A2, b23.x); ffma2(acc[2][3], A2, b23.y);
            ffma2(acc[3][0], A3, b01.x); ffma2(acc[3][1], A3, b01.y);
            ffma2(acc[3][2], A3, b23.x); ffma2(acc[3][3], A3, b23.y);
        }

        #pragma unroll
        for (int m = 0; m < 4; ++m) {
            int erow = mg * 4 + m;
            #pragma unroll
            for (int q = 0; q < 4; ++q) {
                float lo, hi;
                unpack2f(acc[m][q], lo, hi);
                int j = lane * 8 + q * 2;
                s_hid[erow * 256 + j]     = gelu_tanh(lo + b1e[j]);
                s_hid[erow * 256 + j + 1] = gelu_tanh(hi + b1e[j + 1]);
            }
        }
    }
    __syncthreads();

    // ---- Phase C: GEMM2  out[32x128] = s_hid @ w2e + b2e ----
    {
        unsigned long long acc[4][2];
        #pragma unroll
        for (int m = 0; m < 4; ++m) { acc[m][0] = 0ull; acc[m][1] = 0ull; }

        const float* h0 = s_hid + (mg * 4 + 0) * 256;
        const float* h1 = s_hid + (mg * 4 + 1) * 256;
        const float* h2 = s_hid + (mg * 4 + 2) * 256;
        const float* h3 = s_hid + (mg * 4 + 3) * 256;
        const char*  wp = (const char*)(w2e + lane * 4);

        #pragma unroll 4
        for (int k = 0; k < 256; ++k) {
            float hv0 = h0[k], hv1 = h1[k], hv2 = h2[k], hv3 = h3[k];
            ulonglong2 b = *(const ulonglong2*)(wp);
            wp += 512;
            unsigned long long H0 = pack2f(hv0, hv0);
            unsigned long long H1 = pack2f(hv1, hv1);
            unsigned long long H2 = pack2f(hv2, hv2);
            unsigned long long H3 = pack2f(hv3, hv3);
            ffma2(acc[0][0], H0, b.x); ffma2(acc[0][1], H0, b.y);
            ffma2(acc[1][0], H1, b.x); ffma2(acc[1][1], H1, b.y);
            ffma2(acc[2][0], H2, b.x); ffma2(acc[2][1], H2, b.y);
            ffma2(acc[3][0], H3, b.x); ffma2(acc[3][1], H3, b.y);
        }

        float bb0 = b2e[lane * 4 + 0];
        float bb1 = b2e[lane * 4 + 1];
        float bb2 = b2e[lane * 4 + 2];
        float bb3 = b2e[lane * 4 + 3];

        #pragma unroll
        for (int m = 0; m < 4; ++m) {
            float o0, o1, o2, o3;
            unpack2f(acc[m][0], o0, o1);
            unpack2f(acc[m][1], o2, o3);
            int eglob = blockIdx.x * TM + mg * 4 + m;
            float4 v = make_float4(o0 + bb0, o1 + bb1, o2 + bb2, o3 + bb3);
            *(float4*)(out + eglob * 128 + lane * 4) = v;
        }
    }
}

// ---------------- launch ----------------------------------------------------
extern "C" void kernel_launch(void* const* d_in, const int* in_sizes, int n_in,
                              void* d_out, int out_size) {
    const float* emb        = (const float*)d_in[0];   // res_embedding_in  [1024,256]
    const float* ts         = (const float*)d_in[1];   // timestep          [1024,1]
    const float* coords     = (const float*)d_in[2];   // coords            [1024,3,3]
    const float* time_freq  = (const float*)d_in[3];   // [16]
    const float* chain_freq = (const float*)d_in[4];   // [32]
    const float* w1_res     = (const float*)d_in[5];   // [288,256]
    const float* b1_res     = (const float*)d_in[6];
    const float* w2_res     = (const float*)d_in[7];   // [256,256]
    const float* b2_res     = (const float*)d_in[8];
    const float* w_geom     = (const float*)d_in[9];   // [27,128]
    const float* w1_edge    = (const float*)d_in[10];  // [704,256]
    const float* b1_edge    = (const float*)d_in[11];
    const float* w2_edge    = (const float*)d_in[12];  // [256,128]
    const float* b2_edge    = (const float*)d_in[13];
    const int*   ri         = (const int*)d_in[14];    // residue_index
    const int*   cid        = (const int*)d_in[15];    // res_chain_id
    const int*   gA         = (const int*)d_in[16];    // gather_idx_ab_a
    const int*   gB         = (const int*)d_in[17];    // gather_idx_ab_b
    const int*   pid        = (const int*)d_in[18];    // gather_idx_pid_a
    float* out = (float*)d_out;

    cudaFuncSetAttribute(edge_kernel, cudaFuncAttributeMaxDynamicSharedMemorySize,
                         SMEM_EDGE_BYTES);

    residue_kernel<<<N_RES, 256>>>(emb, ts, time_freq, w1_res, b1_res, w2_res, b2_res);
    frames_kernel<<<(N_RES + 255) / 256, 256>>>(coords);
    edge_kernel<<<EDGE_BLOCKS, 256, SMEM_EDGE_BYTES>>>(
        w_geom, chain_freq, w1_edge, b1_edge, w2_edge, b2_edge,
        ri, cid, gA, gB, pid, out);
}

// round 4
// speedup vs baseline: 2.6340x; 2.6340x over previous
#include <cuda_runtime.h>
#include <cuda_fp16.h>
#include <cstdint>
#include <math.h>

#define N_RES   1024
#define NB      15
#define E_AB_LO 131072
#define E_TOT   133120
#define EPSF    1e-6f
#define TWO_PI  6.283185307179586f

#define EPB     64
#define EDGE_BLOCKS (E_TOT / EPB)     // 2080
#define LDA     712                   // s_in row stride (halves)
#define LDB     264                   // B chunk row stride
#define LDH     264                   // hidden row stride
#define LDB2    136                   // B2 chunk row stride

// smem byte offsets
#define SO_IN    0
#define SO_HID   91136
#define SO_B     124928               // 2 x 33792
#define SO_GI    192512               // 64*28*4 = 7168
#define SO_META  199680               // src/dst/disp/scl 4*256
#define SO_B1    200704               // 1024
#define SO_B2    201728               // 512
#define SMEM_EDGE 202240

__device__ __half g_reph[N_RES * 256];
__device__ float  g_R[N_RES * 9];
__device__ float  g_t[N_RES * 3];
__device__ __half g_w1h[704 * 256];
__device__ __half g_w2h[256 * 128];

// ---------- helpers ----------
__device__ __forceinline__ uint32_t smem_u32(const void* p) {
    uint32_t a;
    asm("{ .reg .u64 t; cvta.to.shared.u64 t, %1; cvt.u32.u64 %0, t; }" : "=r"(a) : "l"(p));
    return a;
}
__device__ __forceinline__ unsigned long long pack2f(float lo, float hi) {
    unsigned long long r; asm("mov.b64 %0, {%1, %2};" : "=l"(r) : "f"(lo), "f"(hi)); return r;
}
__device__ __forceinline__ void unpack2f(unsigned long long v, float& lo, float& hi) {
    asm("mov.b64 {%0, %1}, %2;" : "=f"(lo), "=f"(hi) : "l"(v));
}
__device__ __forceinline__ void ffma2(unsigned long long& d, unsigned long long a, unsigned long long b) {
    asm("fma.rn.f32x2 %0, %1, %2, %0;" : "+l"(d) : "l"(a), "l"(b));
}
__device__ __forceinline__ void ldmx4(uint32_t* r, uint32_t addr) {
    asm volatile("ldmatrix.sync.aligned.m8n8.x4.shared.b16 {%0,%1,%2,%3}, [%4];"
        : "=r"(r[0]), "=r"(r[1]), "=r"(r[2]), "=r"(r[3]) : "r"(addr));
}
__device__ __forceinline__ void ldmx4t(uint32_t* r, uint32_t addr) {
    asm volatile("ldmatrix.sync.aligned.m8n8.x4.trans.shared.b16 {%0,%1,%2,%3}, [%4];"
        : "=r"(r[0]), "=r"(r[1]), "=r"(r[2]), "=r"(r[3]) : "r"(addr));
}
__device__ __forceinline__ void mma16816(float* d, const uint32_t* a, uint32_t b0, uint32_t b1) {
    asm volatile("mma.sync.aligned.m16n8k16.row.col.f32.f16.f16.f32 "
        "{%0,%1,%2,%3},{%4,%5,%6,%7},{%8,%9},{%0,%1,%2,%3};"
        : "+f"(d[0]), "+f"(d[1]), "+f"(d[2]), "+f"(d[3])
        : "r"(a[0]), "r"(a[1]), "r"(a[2]), "r"(a[3]), "r"(b0), "r"(b1));
}
__device__ __forceinline__ float gelu_tanh(float x) {
    float x3 = x * x * x;
    return 0.5f * x * (1.0f + tanhf(0.7978845608028654f * (x + 0.044715f * x3)));
}

// ---------- residue MLP: 8 rows/block ----------
__global__ void __launch_bounds__(256) residue_kernel(
        const float* __restrict__ emb, const float* __restrict__ ts,
        const float* __restrict__ tf,  const float* __restrict__ w1,
        const float* __restrict__ b1,  const float* __restrict__ w2,
        const float* __restrict__ b2) {
    __shared__ float sx[8 * 288];
    __shared__ float sh[8 * 256];
    const int t = threadIdx.x, r0 = blockIdx.x * 8;
    #pragma unroll
    for (int i = 0; i < 9; ++i) {
        int idx = t + i * 256;
        int row = idx / 288, col = idx - row * 288;
        float v;
        if (col < 256) v = emb[(r0 + row) * 256 + col];
        else {
            int cc = col - 256;
            float ang = TWO_PI * ts[r0 + row] * tf[cc & 15];
            v = (cc < 16) ? sinf(ang) : cosf(ang);
        }
        sx[row * 288 + col] = v;
    }
    __syncthreads();
    const int row = t >> 5, c0 = (t & 31) * 8;
    unsigned long long a[4] = {0ull, 0ull, 0ull, 0ull};
    #pragma unroll 4
    for (int k = 0; k < 288; ++k) {
        float s = sx[row * 288 + k];
        unsigned long long A = pack2f(s, s);
        ulonglong2 w0 = *(const ulonglong2*)(w1 + k * 256 + c0);
        ulonglong2 w1v = *(const ulonglong2*)(w1 + k * 256 + c0 + 4);
        ffma2(a[0], A, w0.x); ffma2(a[1], A, w0.y);
        ffma2(a[2], A, w1v.x); ffma2(a[3], A, w1v.y);
    }
    #pragma unroll
    for (int q = 0; q < 4; ++q) {
        float lo, hi; unpack2f(a[q], lo, hi);
        sh[row * 256 + c0 + 2 * q]     = gelu_tanh(lo + b1[c0 + 2 * q]);
        sh[row * 256 + c0 + 2 * q + 1] = gelu_tanh(hi + b1[c0 + 2 * q + 1]);
    }
    __syncthreads();
    unsigned long long a2[4] = {0ull, 0ull, 0ull, 0ull};
    #pragma unroll 4
    for (int k = 0; k < 256; ++k) {
        float s = sh[row * 256 + k];
        unsigned long long A = pack2f(s, s);
        ulonglong2 w0 = *(const ulonglong2*)(w2 + k * 256 + c0);
        ulonglong2 w1v = *(const ulonglong2*)(w2 + k * 256 + c0 + 4);
        ffma2(a2[0], A, w0.x); ffma2(a2[1], A, w0.y);
        ffma2(a2[2], A, w1v.x); ffma2(a2[3], A, w1v.y);
    }
    #pragma unroll
    for (int q = 0; q < 4; ++q) {
        float lo, hi; unpack2f(a2[q], lo, hi);
        int j = c0 + 2 * q;
        g_reph[(r0 + row) * 256 + j]     = __float2half(lo + b2[j]     + sx[row * 288 + j]);
        g_reph[(r0 + row) * 256 + j + 1] = __float2half(hi + b2[j + 1] + sx[row * 288 + j + 1]);
    }
}

// ---------- frames ----------
__global__ void frames_kernel(const float* __restrict__ coords) {
    int n = blockIdx.x * blockDim.x + threadIdx.x;
    if (n >= N_RES) return;
    const float* c = coords + n * 9;
    float ax=c[0],ay=c[1],az=c[2], bx=c[3],by=c[4],bz=c[5], cx=c[6],cy=c[7],cz=c[8];
    float v1x=cx-bx,v1y=cy-by,v1z=cz-bz, v2x=ax-bx,v2y=ay-by,v2z=az-bz;
    float n1 = sqrtf(v1x*v1x+v1y*v1y+v1z*v1z) + EPSF;
    float e1x=v1x/n1,e1y=v1y/n1,e1z=v1z/n1;
    float dp = e1x*v2x+e1y*v2y+e1z*v2z;
    float u2x=v2x-e1x*dp,u2y=v2y-e1y*dp,u2z=v2z-e1z*dp;
    float n2 = sqrtf(u2x*u2x+u2y*u2y+u2z*u2z) + EPSF;
    float e2x=u2x/n2,e2y=u2y/n2,e2z=u2z/n2;
    float e3x=e1y*e2z-e1z*e2y, e3y=e1z*e2x-e1x*e2z, e3z=e1x*e2y-e1y*e2x;
    float* R = g_R + n * 9;
    R[0]=e1x;R[1]=e2x;R[2]=e3x; R[3]=e1y;R[4]=e2y;R[5]=e3y; R[6]=e1z;R[7]=e2z;R[8]=e3z;
    g_t[n*3+0]=bx; g_t[n*3+1]=by; g_t[n*3+2]=bz;
}

// ---------- weight prep (fp16 convert) ----------
__global__ void prep_w1(const float* __restrict__ w) {
    int i = blockIdx.x * 256 + threadIdx.x;
    g_w1h[i] = __float2half(w[i]);
}
__global__ void prep_w2(const float* __restrict__ w) {
    int i = blockIdx.x * 256 + threadIdx.x;
    g_w2h[i] = __float2half(w[i]);
}

// ---------- fused edge kernel ----------
__global__ void __launch_bounds__(256, 1)
edge_kernel(const float* __restrict__ w_geom, const float* __restrict__ chain_freq,
            const float* __restrict__ b1e, const float* __restrict__ b2e,
            const int* __restrict__ ri, const int* __restrict__ cid,
            const int* __restrict__ gA, const int* __restrict__ gB,
            const int* __restrict__ pid, float* __restrict__ out) {
    extern __shared__ char smem[];
    const uint32_t sb = smem_u32(smem);
    const int t = threadIdx.x, wid = t >> 5, lane = t & 31;

    __half* s_in_h  = (__half*)(smem + SO_IN);
    __half* s_hid_h = (__half*)(smem + SO_HID);
    __half* s_bh    = (__half*)(smem + SO_B);
    float*  s_gi    = (float*)(smem + SO_GI);
    int*    s_src   = (int*)(smem + SO_META);
    int*    s_dst   = s_src + 64;
    float*  s_dsp   = (float*)(s_dst + 64);
    float*  s_scl   = s_dsp + 64;
    float*  s_b1    = (float*)(smem + SO_B1);
    float*  s_b2    = (float*)(smem + SO_B2);

    s_b1[t] = b1e[t];
    if (t < 128) s_b2[t] = b2e[t];

    // ---- meta + geom inputs (t < 64) ----
    if (t < EPB) {
        int e = blockIdx.x * EPB + t, src, dst;
        if (e < E_AB_LO) { src = gA[e]; dst = gB[e]; }
        else {
            int r = e - E_AB_LO, bb = r >> 10, w = r & 1023;
            src = pid[bb * 32 + (w >> 5)];
            dst = pid[bb * 32 + (w & 31)];
        }
        s_src[t] = src; s_dst[t] = dst;
        float disp = (float)(ri[src] - ri[dst]) * 0.125f;
        s_dsp[t] = disp;
        s_scl[t] = ((cid[src] == cid[dst]) ? 1.0f : 0.0f) / (fabsf(disp) + 1.0f);
        float Rs[9], Rd[9];
        #pragma unroll
        for (int i = 0; i < 9; ++i) { Rs[i] = g_R[src*9+i]; Rd[i] = g_R[dst*9+i]; }
        float dx = g_t[dst*3+0]-g_t[src*3+0], dy = g_t[dst*3+1]-g_t[src*3+1], dz = g_t[dst*3+2]-g_t[src*3+2];
        float dist = sqrtf(dx*dx + dy*dy + dz*dz + EPSF);
        float* gi = s_gi + t * 28;
        #pragma unroll
        for (int i = 0; i < NB; ++i) {
            float z = (dist - (20.0f/14.0f)*(float)i) * 0.75f;
            gi[i] = expf(-0.5f * z * z);
        }
        #pragma unroll
        for (int a = 0; a < 3; ++a)
            #pragma unroll
            for (int b = 0; b < 3; ++b)
                gi[15 + a*3 + b] = Rs[a]*Rd[b] + Rs[3+a]*Rd[3+b] + Rs[6+a]*Rd[6+b];
        float inv = 1.0f / (dist + 1.0f);
        #pragma unroll
        for (int k = 0; k < 3; ++k)
            gi[24 + k] = (Rs[k]*dx + Rs[3+k]*dy + Rs[6+k]*dz) * inv;
    }
    __syncthreads();

    // ---- features -> s_in (fp16) ----
    {   // geom cols 0..127
        const int e = t >> 2, p = t & 3;
        float acc[32];
        #pragma unroll
        for (int j = 0; j < 32; ++j) acc[j] = 0.0f;
        const float* gi = s_gi + e * 28;
        #pragma unroll
        for (int k = 0; k < 27; ++k) {
            float g = gi[k];
            const float4* wg = (const float4*)(w_geom + k * 128 + p * 32);
            #pragma unroll
            for (int q = 0; q < 8; ++q) {
                float4 w4 = wg[q];
                acc[4*q+0] += g * w4.x; acc[4*q+1] += g * w4.y;
                acc[4*q+2] += g * w4.z; acc[4*q+3] += g * w4.w;
            }
        }
        __half2* drow = (__half2*)(s_in_h + e * LDA + p * 32);
        #pragma unroll
        for (int j = 0; j < 16; ++j) drow[j] = __floats2half2_rn(acc[2*j], acc[2*j+1]);
    }
    {   // rope cols 128..191
        const int e = t >> 2, p = t & 3;
        float dsp = s_dsp[e], sc = s_scl[e];
        __half2* drow = (__half2*)(s_in_h + e * LDA + 128 + p * 16);
        #pragma unroll
        for (int u = 0; u < 8; ++u) {
            int i0 = p * 16 + 2*u, i1 = i0 + 1;
            float a0 = TWO_PI * dsp * __ldg(chain_freq + (i0 & 31));
            float a1 = TWO_PI * dsp * __ldg(chain_freq + (i1 & 31));
            float v0 = ((i0 < 32) ? sinf(a0) : cosf(a0)) * sc;
            float v1 = ((i1 < 32) ? sinf(a1) : cosf(a1)) * sc;
            drow[u] = __floats2half2_rn(v0, v1);
        }
    }
    {   // rep gather cols 192..703
        #pragma unroll
        for (int i = 0; i < 16; ++i) {
            int v = t + i * 256;
            int e = v >> 6, q = v & 63;
            int idx = (q < 32) ? s_src[e] : s_dst[e];
            uint4 val = *(const uint4*)(g_reph + idx * 256 + (q & 31) * 8);
            *(uint4*)(s_in_h + e * LDA + 192 + q * 8) = val;
        }
    }
    {   // prefetch B chunk 0
        int r = t >> 2, part = t & 3;
        const uint4* s4 = (const uint4*)(g_w1h + r * 256 + part * 64);
        uint4* d4 = (uint4*)(s_bh + r * LDB + part * 64);
        #pragma unroll
        for (int q = 0; q < 8; ++q) d4[q] = s4[q];
    }
    __syncthreads();

    // ---- GEMM1: [64 x 704] x [704 x 256], 11 chunks of K=64 ----
    const int wm = wid & 1, wn = wid >> 1;
    const int m0 = wm * 32;
    float acc[2][8][4];
    #pragma unroll
    for (int s = 0; s < 2; ++s)
        #pragma unroll
        for (int n = 0; n < 8; ++n)
            #pragma unroll
            for (int q = 0; q < 4; ++q) acc[s][n][q] = 0.0f;

    for (int c = 0; c < 11; ++c) {
        if (c + 1 < 11) {   // prefetch next chunk into other buffer
            int r = t >> 2, part = t & 3;
            const uint4* s4 = (const uint4*)(g_w1h + ((c + 1) * 64 + r) * 256 + part * 64);
            uint4* d4 = (uint4*)(s_bh + ((c + 1) & 1) * 16896 + r * LDB + part * 64);
            #pragma unroll
            for (int q = 0; q < 8; ++q) d4[q] = s4[q];
        }
        const uint32_t Bbase = sb + SO_B + (c & 1) * 33792;
        #pragma unroll
        for (int ks = 0; ks < 4; ++ks) {
            uint32_t a[2][4];
            #pragma unroll
            for (int sub = 0; sub < 2; ++sub) {
                uint32_t row = m0 + sub * 16 + (lane & 15);
                uint32_t col = c * 64 + ks * 16 + (lane >> 4) * 8;
                ldmx4(a[sub], sb + SO_IN + (row * LDA + col) * 2);
            }
            #pragma unroll
            for (int np = 0; np < 4; ++np) {
                uint32_t krow = ks * 16 + (lane & 15);
                uint32_t ncol = wn * 64 + np * 16 + (lane >> 4) * 8;
                uint32_t b[4];
                ldmx4t(b, Bbase + (krow * LDB + ncol) * 2);
                mma16816(acc[0][np*2],   a[0], b[0], b[1]);
                mma16816(acc[0][np*2+1], a[0], b[2], b[3]);
                mma16816(acc[1][np*2],   a[1], b[0], b[1]);
                mma16816(acc[1][np*2+1], a[1], b[2], b[3]);
            }
        }
        __syncthreads();
    }

    // ---- epilogue 1: bias + gelu -> s_hid (fp16), prefetch B2 chunk 0 ----
    {
        const int r0 = m0 + (lane >> 2);
        const int cb = wn * 64 + (lane & 3) * 2;
        #pragma unroll
        for (int sub = 0; sub < 2; ++sub) {
            int rA = r0 + sub * 16;
            #pragma unroll
            for (int nt = 0; nt < 8; ++nt) {
                int col = cb + nt * 8;
                float bb0 = s_b1[col], bb1 = s_b1[col + 1];
                float* A = acc[sub][nt];
                *(__half2*)(s_hid_h + rA * LDH + col) =
                    __floats2half2_rn(gelu_tanh(A[0] + bb0), gelu_tanh(A[1] + bb1));
                *(__half2*)(s_hid_h + (rA + 8) * LDH + col) =
                    __floats2half2_rn(gelu_tanh(A[2] + bb0), gelu_tanh(A[3] + bb1));
            }
        }
        int r = t >> 2, part = t & 3;
        const uint4* s4 = (const uint4*)(g_w2h + r * 128 + part * 32);
        uint4* d4 = (uint4*)(s_bh + r * LDB2 + part * 32);
        #pragma unroll
        for (int q = 0; q < 4; ++q) d4[q] = s4[q];
    }
    __syncthreads();

    // ---- GEMM2: [64 x 256] x [256 x 128], 4 chunks of K=64 ----
    float acc2[2][4][4];
    #pragma unroll
    for (int s = 0; s < 2; ++s)
        #pragma unroll
        for (int n = 0; n < 4; ++n)
            #pragma unroll
            for (int q = 0; q < 4; ++q) acc2[s][n][q] = 0.0f;

    for (int c = 0; c < 4; ++c) {
        if (c + 1 < 4) {
            int r = t >> 2, part = t & 3;
            const uint4* s4 = (const uint4*)(g_w2h + ((c + 1) * 64 + r) * 128 + part * 32);
            uint4* d4 = (uint4*)(s_bh + ((c + 1) & 1) * 16896 + r * LDB2 + part * 32);
            #pragma unroll
            for (int q = 0; q < 4; ++q) d4[q] = s4[q];
        }
        const uint32_t Bbase = sb + SO_B + (c & 1) * 33792;
        #pragma unroll
        for (int ks = 0; ks < 4; ++ks) {
            uint32_t a[2][4];
            #pragma unroll
            for (int sub = 0; sub < 2; ++sub) {
                uint32_t row = m0 + sub * 16 + (lane & 15);
                uint32_t col = c * 64 + ks * 16 + (lane >> 4) * 8;
                ldmx4(a[sub], sb + SO_HID + (row * LDH + col) * 2);
            }
            #pragma unroll
            for (int np = 0; np < 2; ++np) {
                uint32_t krow = ks * 16 + (lane & 15);
                uint32_t ncol = wn * 32 + np * 16 + (lane >> 4) * 8;
                uint32_t b[4];
                ldmx4t(b, Bbase + (krow * LDB2 + ncol) * 2);
                mma16816(acc2[0][np*2],   a[0], b[0], b[1]);
                mma16816(acc2[0][np*2+1], a[0], b[2], b[3]);
                mma16816(acc2[1][np*2],   a[1], b[0], b[1]);
                mma16816(acc2[1][np*2+1], a[1], b[2], b[3]);
            }
        }
        __syncthreads();
    }

    // ---- epilogue 2: bias + store fp32 ----
    {
        const int r0 = m0 + (lane >> 2);
        const int cb = wn * 32 + (lane & 3) * 2;
        #pragma unroll
        for (int sub = 0; sub < 2; ++sub) {
            int rA = r0 + sub * 16;
            int eg0 = blockIdx.x * EPB + rA;
            #pragma unroll
            for (int nt = 0; nt < 4; ++nt) {
                int col = cb + nt * 8;
                float bb0 = s_b2[col], bb1 = s_b2[col + 1];
                float* A = acc2[sub][nt];
                *(float2*)(out + eg0 * 128 + col)       = make_float2(A[0] + bb0, A[1] + bb1);
                *(float2*)(out + (eg0 + 8) * 128 + col) = make_float2(A[2] + bb0, A[3] + bb1);
            }
        }
    }
}

// ---------- launch ----------
extern "C" void kernel_launch(void* const* d_in, const int* in_sizes, int n_in,
                              void* d_out, int out_size) {
    const float* emb        = (const float*)d_in[0];
    const float* ts         = (const float*)d_in[1];
    const float* coords     = (const float*)d_in[2];
    const float* time_freq  = (const float*)d_in[3];
    const float* chain_freq = (const float*)d_in[4];
    const float* w1_res     = (const float*)d_in[5];
    const float* b1_res     = (const float*)d_in[6];
    const float* w2_res     = (const float*)d_in[7];
    const float* b2_res     = (const float*)d_in[8];
    const float* w_geom     = (const float*)d_in[9];
    const float* w1_edge    = (const float*)d_in[10];
    const float* b1_edge    = (const float*)d_in[11];
    const float* w2_edge    = (const float*)d_in[12];
    const float* b2_edge    = (const float*)d_in[13];
    const int*   ri         = (const int*)d_in[14];
    const int*   cid        = (const int*)d_in[15];
    const int*   gA         = (const int*)d_in[16];
    const int*   gB         = (const int*)d_in[17];
    const int*   pid        = (const int*)d_in[18];
    float* out = (float*)d_out;

    cudaFuncSetAttribute(edge_kernel, cudaFuncAttributeMaxDynamicSharedMemorySize, SMEM_EDGE);

    residue_kernel<<<128, 256>>>(emb, ts, time_freq, w1_res, b1_res, w2_res, b2_res);
    frames_kernel<<<4, 256>>>(coords);
    prep_w1<<<704, 256>>>(w1_edge);
    prep_w2<<<128, 256>>>(w2_edge);
    edge_kernel<<<EDGE_BLOCKS, 256, SMEM_EDGE>>>(
        w_geom, chain_freq, b1_edge, b2_edge, ri, cid, gA, gB, pid, out);
}

// round 5
// speedup vs baseline: 3.8814x; 1.4736x over previous
#include <cuda_runtime.h>
#include <cuda_fp16.h>
#include <cstdint>
#include <math.h>

#define N_RES   1024
#define NB      15
#define E_AB_LO 131072
#define E_TOT   133120
#define EPSF    1e-6f
#define TWO_PI  6.283185307179586f

#define EPB     64
#define EDGE_BLOCKS (E_TOT / EPB)     // 2080

// smem byte offsets
#define SO_A    0                     // 2 x 64x40 half = 10240
#define SO_B    10240                 // 2 x 16896 = 33792
#define SO_HID  44032                 // 64 x 264 half = 33792
#define SO_GI   77824                 // 64*28*4 = 7168
#define SO_META 84992                 // 1024
#define SO_B1   86016                 // 1024
#define SO_B2   87040                 // 512
#define SMEM_EDGE 87552

__device__ __half g_reph[N_RES * 256];
__device__ float  g_R[N_RES * 9];
__device__ float  g_t[N_RES * 3];
__device__ __half g_w1h[704 * 256];
__device__ __half g_w2h[256 * 128];

// ---------- helpers ----------
__device__ __forceinline__ uint32_t smem_u32(const void* p) {
    uint32_t a;
    asm("{ .reg .u64 t; cvta.to.shared.u64 t, %1; cvt.u32.u64 %0, t; }" : "=r"(a) : "l"(p));
    return a;
}
__device__ __forceinline__ unsigned long long pack2f(float lo, float hi) {
    unsigned long long r; asm("mov.b64 %0, {%1, %2};" : "=l"(r) : "f"(lo), "f"(hi)); return r;
}
__device__ __forceinline__ void unpack2f(unsigned long long v, float& lo, float& hi) {
    asm("mov.b64 {%0, %1}, %2;" : "=f"(lo), "=f"(hi) : "l"(v));
}
__device__ __forceinline__ void ffma2(unsigned long long& d, unsigned long long a, unsigned long long b) {
    asm("fma.rn.f32x2 %0, %1, %2, %0;" : "+l"(d) : "l"(a), "l"(b));
}
__device__ __forceinline__ void ldmx4(uint32_t* r, uint32_t addr) {
    asm volatile("ldmatrix.sync.aligned.m8n8.x4.shared.b16 {%0,%1,%2,%3}, [%4];"
        : "=r"(r[0]), "=r"(r[1]), "=r"(r[2]), "=r"(r[3]) : "r"(addr));
}
__device__ __forceinline__ void ldmx4t(uint32_t* r, uint32_t addr) {
    asm volatile("ldmatrix.sync.aligned.m8n8.x4.trans.shared.b16 {%0,%1,%2,%3}, [%4];"
        : "=r"(r[0]), "=r"(r[1]), "=r"(r[2]), "=r"(r[3]) : "r"(addr));
}
__device__ __forceinline__ void mma16816(float* d, const uint32_t* a, uint32_t b0, uint32_t b1) {
    asm volatile("mma.sync.aligned.m16n8k16.row.col.f32.f16.f16.f32 "
        "{%0,%1,%2,%3},{%4,%5,%6,%7},{%8,%9},{%0,%1,%2,%3};"
        : "+f"(d[0]), "+f"(d[1]), "+f"(d[2]), "+f"(d[3])
        : "r"(a[0]), "r"(a[1]), "r"(a[2]), "r"(a[3]), "r"(b0), "r"(b1));
}
__device__ __forceinline__ void cpa16(uint32_t dst, const void* src) {
    asm volatile("cp.async.cg.shared.global [%0], [%1], 16;" :: "r"(dst), "l"(src));
}
#define CP_COMMIT() asm volatile("cp.async.commit_group;" ::: "memory")
#define CP_WAIT0()  asm volatile("cp.async.wait_group 0;" ::: "memory")

__device__ __forceinline__ float gelu_tanh(float x) {
    float x3 = x * x * x;
    return 0.5f * x * (1.0f + tanhf(0.7978845608028654f * (x + 0.044715f * x3)));
}

// ---------- residue MLP ----------
__global__ void __launch_bounds__(256) residue_kernel(
        const float* __restrict__ emb, const float* __restrict__ ts,
        const float* __restrict__ tf,  const float* __restrict__ w1,
        const float* __restrict__ b1,  const float* __restrict__ w2,
        const float* __restrict__ b2) {
    __shared__ float sx[8 * 288];
    __shared__ float sh[8 * 256];
    const int t = threadIdx.x, r0 = blockIdx.x * 8;
    #pragma unroll
    for (int i = 0; i < 9; ++i) {
        int idx = t + i * 256;
        int row = idx / 288, col = idx - row * 288;
        float v;
        if (col < 256) v = emb[(r0 + row) * 256 + col];
        else {
            int cc = col - 256;
            float ang = TWO_PI * ts[r0 + row] * tf[cc & 15];
            v = (cc < 16) ? sinf(ang) : cosf(ang);
        }
        sx[row * 288 + col] = v;
    }
    __syncthreads();
    const int row = t >> 5, c0 = (t & 31) * 8;
    unsigned long long a[4] = {0ull, 0ull, 0ull, 0ull};
    #pragma unroll 4
    for (int k = 0; k < 288; ++k) {
        float s = sx[row * 288 + k];
        unsigned long long A = pack2f(s, s);
        ulonglong2 w0 = *(const ulonglong2*)(w1 + k * 256 + c0);
        ulonglong2 w1v = *(const ulonglong2*)(w1 + k * 256 + c0 + 4);
        ffma2(a[0], A, w0.x); ffma2(a[1], A, w0.y);
        ffma2(a[2], A, w1v.x); ffma2(a[3], A, w1v.y);
    }
    #pragma unroll
    for (int q = 0; q < 4; ++q) {
        float lo, hi; unpack2f(a[q], lo, hi);
        sh[row * 256 + c0 + 2 * q]     = gelu_tanh(lo + b1[c0 + 2 * q]);
        sh[row * 256 + c0 + 2 * q + 1] = gelu_tanh(hi + b1[c0 + 2 * q + 1]);
    }
    __syncthreads();
    unsigned long long a2[4] = {0ull, 0ull, 0ull, 0ull};
    #pragma unroll 4
    for (int k = 0; k < 256; ++k) {
        float s = sh[row * 256 + k];
        unsigned long long A = pack2f(s, s);
        ulonglong2 w0 = *(const ulonglong2*)(w2 + k * 256 + c0);
        ulonglong2 w1v = *(const ulonglong2*)(w2 + k * 256 + c0 + 4);
        ffma2(a2[0], A, w0.x); ffma2(a2[1], A, w0.y);
        ffma2(a2[2], A, w1v.x); ffma2(a2[3], A, w1v.y);
    }
    #pragma unroll
    for (int q = 0; q < 4; ++q) {
        float lo, hi; unpack2f(a2[q], lo, hi);
        int j = c0 + 2 * q;
        g_reph[(r0 + row) * 256 + j]     = __float2half(lo + b2[j]     + sx[row * 288 + j]);
        g_reph[(r0 + row) * 256 + j + 1] = __float2half(hi + b2[j + 1] + sx[row * 288 + j + 1]);
    }
}

// ---------- aux: frames + weight fp16 conversion (one kernel) ----------
__global__ void aux_kernel(const float* __restrict__ coords,
                           const float* __restrict__ w1e,
                           const float* __restrict__ w2e) {
    int g = blockIdx.x * 256 + threadIdx.x;
    if (g < 704 * 256) g_w1h[g] = __float2half(w1e[g]);
    else {
        int h = g - 704 * 256;
        g_w2h[h] = __float2half(w2e[h]);
    }
    if (g < N_RES) {
        const float* c = coords + g * 9;
        float ax=c[0],ay=c[1],az=c[2], bx=c[3],by=c[4],bz=c[5], cx=c[6],cy=c[7],cz=c[8];
        float v1x=cx-bx,v1y=cy-by,v1z=cz-bz, v2x=ax-bx,v2y=ay-by,v2z=az-bz;
        float n1 = sqrtf(v1x*v1x+v1y*v1y+v1z*v1z) + EPSF;
        float e1x=v1x/n1,e1y=v1y/n1,e1z=v1z/n1;
        float dp = e1x*v2x+e1y*v2y+e1z*v2z;
        float u2x=v2x-e1x*dp,u2y=v2y-e1y*dp,u2z=v2z-e1z*dp;
        float n2 = sqrtf(u2x*u2x+u2y*u2y+u2z*u2z) + EPSF;
        float e2x=u2x/n2,e2y=u2y/n2,e2z=u2z/n2;
        float e3x=e1y*e2z-e1z*e2y, e3y=e1z*e2x-e1x*e2z, e3z=e1x*e2y-e1y*e2x;
        float* R = g_R + g * 9;
        R[0]=e1x;R[1]=e2x;R[2]=e3x; R[3]=e1y;R[4]=e2y;R[5]=e3y; R[6]=e1z;R[7]=e2z;R[8]=e3z;
        g_t[g*3+0]=bx; g_t[g*3+1]=by; g_t[g*3+2]=bz;
    }
}

// ---------- A chunk staging (K=32 per chunk; 22 chunks) ----------
__device__ __forceinline__ void stageA(int c, int t, uint32_t abuf_u32, __half* abuf_h,
        const float* s_gi, const int* s_src, const int* s_dst,
        const float* s_dsp, const float* s_scl,
        const float* __restrict__ w_geom, const float* __restrict__ chain_freq) {
    const int e = t >> 2, p = t & 3;
    if (c >= 6) {                      // rep copy: cols 192..703
        int idx = (c < 14) ? s_src[e] : s_dst[e];
        int off = (c < 14) ? (c - 6) * 32 : (c - 14) * 32;
        cpa16(abuf_u32 + e * 80 + p * 16, g_reph + idx * 256 + off + p * 8);
    } else if (c >= 4) {               // rope: cols 128..191
        float dsp = s_dsp[e], sc = s_scl[e];
        __half2 h[4];
        if (sc == 0.0f) {
            #pragma unroll
            for (int j = 0; j < 4; ++j) h[j] = __floats2half2_rn(0.0f, 0.0f);
        } else {
            #pragma unroll
            for (int j = 0; j < 4; ++j) {
                int i0 = (c - 4) * 32 + p * 8 + 2 * j, i1 = i0 + 1;
                float a0 = TWO_PI * dsp * __ldg(chain_freq + (i0 & 31));
                float a1 = TWO_PI * dsp * __ldg(chain_freq + (i1 & 31));
                float v0 = ((i0 < 32) ? sinf(a0) : cosf(a0)) * sc;
                float v1 = ((i1 < 32) ? sinf(a1) : cosf(a1)) * sc;
                h[j] = __floats2half2_rn(v0, v1);
            }
        }
        *(uint4*)(abuf_h + e * 40 + p * 8) = *(uint4*)h;
    } else {                           // geom: cols 0..127
        const float* gi = s_gi + e * 28;
        float a8[8];
        #pragma unroll
        for (int j = 0; j < 8; ++j) a8[j] = 0.0f;
        const float* wg0 = w_geom + c * 32 + p * 8;
        #pragma unroll
        for (int k = 0; k < 27; ++k) {
            float g = gi[k];
            const float4* wg = (const float4*)(wg0 + k * 128);
            float4 w0 = wg[0], w1 = wg[1];
            a8[0]+=g*w0.x; a8[1]+=g*w0.y; a8[2]+=g*w0.z; a8[3]+=g*w0.w;
            a8[4]+=g*w1.x; a8[5]+=g*w1.y; a8[6]+=g*w1.z; a8[7]+=g*w1.w;
        }
        __half2 h[4];
        #pragma unroll
        for (int j = 0; j < 4; ++j) h[j] = __floats2half2_rn(a8[2*j], a8[2*j+1]);
        *(uint4*)(abuf_h + e * 40 + p * 8) = *(uint4*)h;
    }
}

// ---------- fused edge kernel: 2 CTAs/SM ----------
__global__ void __launch_bounds__(256, 2)
edge_kernel(const float* __restrict__ w_geom, const float* __restrict__ chain_freq,
            const float* __restrict__ b1e, const float* __restrict__ b2e,
            const int* __restrict__ ri, const int* __restrict__ cid,
            const int* __restrict__ gA, const int* __restrict__ gB,
            const int* __restrict__ pid, float* __restrict__ out) {
    extern __shared__ char smem[];
    const uint32_t sb = smem_u32(smem);
    const int t = threadIdx.x, wid = t >> 5, lane = t & 31;
    const int wm = wid & 1, wn = wid >> 1, m0 = wm * 32;

    float* s_gi  = (float*)(smem + SO_GI);
    int*   s_src = (int*)(smem + SO_META);
    int*   s_dst = s_src + 64;
    float* s_dsp = (float*)(s_dst + 64);
    float* s_scl = s_dsp + 64;
    float* s_b1  = (float*)(smem + SO_B1);
    float* s_b2  = (float*)(smem + SO_B2);
    __half* s_hid = (__half*)(smem + SO_HID);

    // prefetch B1 chunk 0 (K rows 0..31) while we compute meta/gi
    {
        int r = t >> 3;
        #pragma unroll
        for (int q = 0; q < 4; ++q) {
            int s = (t & 7) * 4 + q;
            cpa16(sb + SO_B + r * 528 + s * 16, g_w1h + r * 256 + s * 8);
        }
        CP_COMMIT();
    }
    s_b1[t] = b1e[t];
    if (t < 128) s_b2[t] = b2e[t];

    if (t < EPB) {
        int e = blockIdx.x * EPB + t, src, dst;
        if (e < E_AB_LO) { src = gA[e]; dst = gB[e]; }
        else {
            int r = e - E_AB_LO, bb = r >> 10, w = r & 1023;
            src = pid[bb * 32 + (w >> 5)];
            dst = pid[bb * 32 + (w & 31)];
        }
        s_src[t] = src; s_dst[t] = dst;
        float disp = (float)(ri[src] - ri[dst]) * 0.125f;
        s_dsp[t] = disp;
        s_scl[t] = ((cid[src] == cid[dst]) ? 1.0f : 0.0f) / (fabsf(disp) + 1.0f);
        float Rs[9], Rd[9];
        #pragma unroll
        for (int i = 0; i < 9; ++i) { Rs[i] = g_R[src*9+i]; Rd[i] = g_R[dst*9+i]; }
        float dx = g_t[dst*3+0]-g_t[src*3+0], dy = g_t[dst*3+1]-g_t[src*3+1], dz = g_t[dst*3+2]-g_t[src*3+2];
        float dist = sqrtf(dx*dx + dy*dy + dz*dz + EPSF);
        float* gi = s_gi + t * 28;
        #pragma unroll
        for (int i = 0; i < NB; ++i) {
            float z = (dist - (20.0f/14.0f)*(float)i) * 0.75f;
            gi[i] = expf(-0.5f * z * z);
        }
        #pragma unroll
        for (int a = 0; a < 3; ++a)
            #pragma unroll
            for (int b = 0; b < 3; ++b)
                gi[15 + a*3 + b] = Rs[a]*Rd[b] + Rs[3+a]*Rd[3+b] + Rs[6+a]*Rd[6+b];
        float inv = 1.0f / (dist + 1.0f);
        #pragma unroll
        for (int k = 0; k < 3; ++k)
            gi[24 + k] = (Rs[k]*dx + Rs[3+k]*dy + Rs[6+k]*dz) * inv;
    }
    __syncthreads();

    // stage A chunk 0 (geom, computed)
    stageA(0, t, sb + SO_A, (__half*)(smem + SO_A), s_gi, s_src, s_dst, s_dsp, s_scl, w_geom, chain_freq);
    CP_COMMIT();
    CP_WAIT0();
    __syncthreads();

    // ---- GEMM1: 22 chunks of K=32 ----
    float acc[2][8][4];
    #pragma unroll
    for (int s = 0; s < 2; ++s)
        #pragma unroll
        for (int n = 0; n < 8; ++n)
            #pragma unroll
            for (int q = 0; q < 4; ++q) acc[s][n][q] = 0.0f;

    for (int c = 0; c < 22; ++c) {
        const int nb = (c + 1) & 1;
        if (c < 21) {
            int r = t >> 3;
            #pragma unroll
            for (int q = 0; q < 4; ++q) {
                int s = (t & 7) * 4 + q;
                cpa16(sb + SO_B + nb * 16896 + r * 528 + s * 16,
                      g_w1h + ((c + 1) * 32 + r) * 256 + s * 8);
            }
            stageA(c + 1, t, sb + SO_A + nb * 5120, (__half*)(smem + SO_A + nb * 5120),
                   s_gi, s_src, s_dst, s_dsp, s_scl, w_geom, chain_freq);
        } else {
            // prefetch B2 chunk 0 into B buf 0
            int r = t >> 3;
            #pragma unroll
            for (int q = 0; q < 2; ++q) {
                int s = (t & 7) * 2 + q;
                cpa16(sb + SO_B + r * 272 + s * 16, g_w2h + r * 128 + s * 8);
            }
        }
        CP_COMMIT();

        const uint32_t Ab = sb + SO_A + (c & 1) * 5120;
        const uint32_t Bb = sb + SO_B + (c & 1) * 16896;
        #pragma unroll
        for (int ks = 0; ks < 2; ++ks) {
            uint32_t a[2][4];
            #pragma unroll
            for (int sub = 0; sub < 2; ++sub)
                ldmx4(a[sub], Ab + (uint32_t)((m0 + sub*16 + (lane & 15)) * 80 + (ks*16 + (lane >> 4) * 8) * 2));
            #pragma unroll
            for (int np = 0; np < 4; ++np) {
                uint32_t b[4];
                ldmx4t(b, Bb + (uint32_t)((ks*16 + (lane & 15)) * 528 + (wn*64 + np*16 + (lane >> 4) * 8) * 2));
                mma16816(acc[0][np*2],   a[0], b[0], b[1]);
                mma16816(acc[0][np*2+1], a[0], b[2], b[3]);
                mma16816(acc[1][np*2],   a[1], b[0], b[1]);
                mma16816(acc[1][np*2+1], a[1], b[2], b[3]);
            }
        }
        CP_WAIT0();
        __syncthreads();
    }

    // ---- epilogue 1: bias + gelu -> s_hid; prefetch B2 chunk 1 ----
    {
        int r = t >> 3;
        #pragma unroll
        for (int q = 0; q < 2; ++q) {
            int s = (t & 7) * 2 + q;
            cpa16(sb + SO_B + 16896 + r * 272 + s * 16, g_w2h + (32 + r) * 128 + s * 8);
        }
        CP_COMMIT();
        const int r0 = m0 + (lane >> 2);
        const int cb = wn * 64 + (lane & 3) * 2;
        #pragma unroll
        for (int sub = 0; sub < 2; ++sub) {
            int rA = r0 + sub * 16;
            #pragma unroll
            for (int nt = 0; nt < 8; ++nt) {
                int col = cb + nt * 8;
                float bb0 = s_b1[col], bb1 = s_b1[col + 1];
                float* A = acc[sub][nt];
                *(__half2*)(s_hid + rA * 264 + col) =
                    __floats2half2_rn(gelu_tanh(A[0] + bb0), gelu_tanh(A[1] + bb1));
                *(__half2*)(s_hid + (rA + 8) * 264 + col) =
                    __floats2half2_rn(gelu_tanh(A[2] + bb0), gelu_tanh(A[3] + bb1));
            }
        }
        CP_WAIT0();
        __syncthreads();
    }

    // ---- GEMM2: 8 chunks of K=32 ----
    float acc2[2][4][4];
    #pragma unroll
    for (int s = 0; s < 2; ++s)
        #pragma unroll
        for (int n = 0; n < 4; ++n)
            #pragma unroll
            for (int q = 0; q < 4; ++q) acc2[s][n][q] = 0.0f;

    for (int d = 0; d < 8; ++d) {
        if (d >= 1 && d < 7) {
            int nb = (d + 1) & 1;
            int r = t >> 3;
            #pragma unroll
            for (int q = 0; q < 2; ++q) {
                int s = (t & 7) * 2 + q;
                cpa16(sb + SO_B + nb * 16896 + r * 272 + s * 16,
                      g_w2h + ((d + 1) * 32 + r) * 128 + s * 8);
            }
        }
        CP_COMMIT();
        const uint32_t Bb = sb + SO_B + (d & 1) * 16896;
        #pragma unroll
        for (int ks = 0; ks < 2; ++ks) {
            uint32_t a[2][4];
            #pragma unroll
            for (int sub = 0; sub < 2; ++sub)
                ldmx4(a[sub], sb + SO_HID +
                    (uint32_t)(((m0 + sub*16 + (lane & 15)) * 264 + d*32 + ks*16 + (lane >> 4) * 8) * 2));
            #pragma unroll
            for (int np = 0; np < 2; ++np) {
                uint32_t b[4];
                ldmx4t(b, Bb + (uint32_t)((ks*16 + (lane & 15)) * 272 + (wn*32 + np*16 + (lane >> 4) * 8) * 2));
                mma16816(acc2[0][np*2],   a[0], b[0], b[1]);
                mma16816(acc2[0][np*2+1], a[0], b[2], b[3]);
                mma16816(acc2[1][np*2],   a[1], b[0], b[1]);
                mma16816(acc2[1][np*2+1], a[1], b[2], b[3]);
            }
        }
        CP_WAIT0();
        __syncthreads();
    }

    // ---- epilogue 2: bias + store ----
    {
        const int r0 = m0 + (lane >> 2);
        const int cb = wn * 32 + (lane & 3) * 2;
        #pragma unroll
        for (int sub = 0; sub < 2; ++sub) {
            int rA = r0 + sub * 16;
            int eg0 = blockIdx.x * EPB + rA;
            #pragma unroll
            for (int nt = 0; nt < 4; ++nt) {
                int col = cb + nt * 8;
                float bb0 = s_b2[col], bb1 = s_b2[col + 1];
                float* A = acc2[sub][nt];
                *(float2*)(out + eg0 * 128 + col)       = make_float2(A[0] + bb0, A[1] + bb1);
                *(float2*)(out + (eg0 + 8) * 128 + col) = make_float2(A[2] + bb0, A[3] + bb1);
            }
        }
    }
}

// ---------- launch ----------
extern "C" void kernel_launch(void* const* d_in, const int* in_sizes, int n_in,
                              void* d_out, int out_size) {
    const float* emb        = (const float*)d_in[0];
    const float* ts         = (const float*)d_in[1];
    const float* coords     = (const float*)d_in[2];
    const float* time_freq  = (const float*)d_in[3];
    const float* chain_freq = (const float*)d_in[4];
    const float* w1_res     = (const float*)d_in[5];
    const float* b1_res     = (const float*)d_in[6];
    const float* w2_res     = (const float*)d_in[7];
    const float* b2_res     = (const float*)d_in[8];
    const float* w_geom     = (const float*)d_in[9];
    const float* w1_edge    = (const float*)d_in[10];
    const float* b1_edge    = (const float*)d_in[11];
    const float* w2_edge    = (const float*)d_in[12];
    const float* b2_edge    = (const float*)d_in[13];
    const int*   ri         = (const int*)d_in[14];
    const int*   cid        = (const int*)d_in[15];
    const int*   gA         = (const int*)d_in[16];
    const int*   gB         = (const int*)d_in[17];
    const int*   pid        = (const int*)d_in[18];
    float* out = (float*)d_out;

    cudaFuncSetAttribute(edge_kernel, cudaFuncAttributeMaxDynamicSharedMemorySize, SMEM_EDGE);

    residue_kernel<<<128, 256>>>(emb, ts, time_freq, w1_res, b1_res, w2_res, b2_res);
    aux_kernel<<<832, 256>>>(coords, w1_edge, w2_edge);
    edge_kernel<<<EDGE_BLOCKS, 256, SMEM_EDGE>>>(
        w_geom, chain_freq, b1_edge, b2_edge, ri, cid, gA, gB, pid, out);
}

// round 6
// speedup vs baseline: 5.1498x; 1.3268x over previous
#include <cuda_runtime.h>
#include <cuda_fp16.h>
#include <cstdint>
#include <math.h>

#define N_RES   1024
#define NB      15
#define E_AB_LO 131072
#define E_TOT   133120
#define EPSF    1e-6f
#define TWO_PI  6.283185307179586f

#define EPB     64
#define EDGE_BLOCKS (E_TOT / EPB)     // 2080

// smem byte offsets (edge kernel)
#define SO_A    0                     // 2 x 64x40 half = 10240
#define SO_B    10240                 // 2 x 16896 = 33792
#define SO_HID  44032                 // 64 x 264 half = 33792
#define SO_GI   77824                 // 64*28*4 = 7168
#define SO_META 84992                 // 1024
#define SO_B1   86016                 // 1024
#define SO_B2   87040                 // 512
#define SMEM_EDGE 87552

__device__ __half g_reph[N_RES * 256];
__device__ float  g_R[N_RES * 9];
__device__ float  g_t[N_RES * 3];
__device__ __half g_w1h[704 * 256];
__device__ __half g_w2h[256 * 128];

// ---------- helpers ----------
__device__ __forceinline__ uint32_t smem_u32(const void* p) {
    uint32_t a;
    asm("{ .reg .u64 t; cvta.to.shared.u64 t, %1; cvt.u32.u64 %0, t; }" : "=r"(a) : "l"(p));
    return a;
}
__device__ __forceinline__ void ldmx4(uint32_t* r, uint32_t addr) {
    asm volatile("ldmatrix.sync.aligned.m8n8.x4.shared.b16 {%0,%1,%2,%3}, [%4];"
        : "=r"(r[0]), "=r"(r[1]), "=r"(r[2]), "=r"(r[3]) : "r"(addr));
}
__device__ __forceinline__ void ldmx4t(uint32_t* r, uint32_t addr) {
    asm volatile("ldmatrix.sync.aligned.m8n8.x4.trans.shared.b16 {%0,%1,%2,%3}, [%4];"
        : "=r"(r[0]), "=r"(r[1]), "=r"(r[2]), "=r"(r[3]) : "r"(addr));
}
__device__ __forceinline__ void mma16816(float* d, const uint32_t* a, uint32_t b0, uint32_t b1) {
    asm volatile("mma.sync.aligned.m16n8k16.row.col.f32.f16.f16.f32 "
        "{%0,%1,%2,%3},{%4,%5,%6,%7},{%8,%9},{%0,%1,%2,%3};"
        : "+f"(d[0]), "+f"(d[1]), "+f"(d[2]), "+f"(d[3])
        : "r"(a[0]), "r"(a[1]), "r"(a[2]), "r"(a[3]), "r"(b0), "r"(b1));
}
__device__ __forceinline__ void cpa16(uint32_t dst, const void* src) {
    asm volatile("cp.async.cg.shared.global [%0], [%1], 16;" :: "r"(dst), "l"(src));
}
#define CP_COMMIT() asm volatile("cp.async.commit_group;" ::: "memory")
#define CP_WAIT0()  asm volatile("cp.async.wait_group 0;" ::: "memory")

__device__ __forceinline__ float gelu_tanh(float x) {
    float x3 = x * x * x;
    return 0.5f * x * (1.0f + tanhf(0.7978845608028654f * (x + 0.044715f * x3)));
}

// ---------- prep kernel: residue MLP (blocks 0..255) + aux (blocks 256..1087) ----------
__global__ void __launch_bounds__(256) prep_kernel(
        const float* __restrict__ emb, const float* __restrict__ ts,
        const float* __restrict__ tf,  const float* __restrict__ w1,
        const float* __restrict__ b1,  const float* __restrict__ w2,
        const float* __restrict__ b2,
        const float* __restrict__ coords,
        const float* __restrict__ w1e, const float* __restrict__ w2e) {
    const int t = threadIdx.x;
    if (blockIdx.x >= 256) {
        int g = (blockIdx.x - 256) * 256 + t;
        if (g < 704 * 256) g_w1h[g] = __float2half(w1e[g]);
        else               g_w2h[g - 704 * 256] = __float2half(w2e[g - 704 * 256]);
        if (g < N_RES) {
            const float* c = coords + g * 9;
            float ax=c[0],ay=c[1],az=c[2], bx=c[3],by=c[4],bz=c[5], cx=c[6],cy=c[7],cz=c[8];
            float v1x=cx-bx,v1y=cy-by,v1z=cz-bz, v2x=ax-bx,v2y=ay-by,v2z=az-bz;
            float n1 = sqrtf(v1x*v1x+v1y*v1y+v1z*v1z) + EPSF;
            float e1x=v1x/n1,e1y=v1y/n1,e1z=v1z/n1;
            float dp = e1x*v2x+e1y*v2y+e1z*v2z;
            float u2x=v2x-e1x*dp,u2y=v2y-e1y*dp,u2z=v2z-e1z*dp;
            float n2 = sqrtf(u2x*u2x+u2y*u2y+u2z*u2z) + EPSF;
            float e2x=u2x/n2,e2y=u2y/n2,e2z=u2z/n2;
            float e3x=e1y*e2z-e1z*e2y, e3y=e1z*e2x-e1x*e2z, e3z=e1x*e2y-e1y*e2x;
            float* R = g_R + g * 9;
            R[0]=e1x;R[1]=e2x;R[2]=e3x; R[3]=e1y;R[4]=e2y;R[5]=e3y; R[6]=e1z;R[7]=e2z;R[8]=e3z;
            g_t[g*3+0]=bx; g_t[g*3+1]=by; g_t[g*3+2]=bz;
        }
        return;
    }
    // ---- residue MLP: 4 rows per block ----
    __shared__ float sx[4 * 288];
    __shared__ float sh[4 * 256];
    const int r0 = blockIdx.x * 4;
    #pragma unroll
    for (int i = 0; i < 5; ++i) {
        int idx = t + i * 256;
        if (idx < 4 * 288) {
            int row = idx / 288, col = idx - row * 288;
            float v;
            if (col < 256) v = emb[(r0 + row) * 256 + col];
            else {
                int cc = col - 256;
                float ang = TWO_PI * ts[r0 + row] * tf[cc & 15];
                v = (cc < 16) ? sinf(ang) : cosf(ang);
            }
            sx[idx] = v;
        }
    }
    __syncthreads();
    float acc[4] = {0.f, 0.f, 0.f, 0.f};
    #pragma unroll 8
    for (int k = 0; k < 288; ++k) {
        float w = __ldg(w1 + k * 256 + t);
        acc[0] += sx[k]       * w;
        acc[1] += sx[288 + k] * w;
        acc[2] += sx[576 + k] * w;
        acc[3] += sx[864 + k] * w;
    }
    float bb = b1[t];
    #pragma unroll
    for (int r = 0; r < 4; ++r) sh[r * 256 + t] = gelu_tanh(acc[r] + bb);
    __syncthreads();
    float ac2[4] = {0.f, 0.f, 0.f, 0.f};
    #pragma unroll 8
    for (int k = 0; k < 256; ++k) {
        float w = __ldg(w2 + k * 256 + t);
        ac2[0] += sh[k]       * w;
        ac2[1] += sh[256 + k] * w;
        ac2[2] += sh[512 + k] * w;
        ac2[3] += sh[768 + k] * w;
    }
    float bb2 = b2[t];
    #pragma unroll
    for (int r = 0; r < 4; ++r)
        g_reph[(r0 + r) * 256 + t] = __float2half(ac2[r] + bb2 + sx[r * 288 + t]);
}

// ---------- A chunk staging (threads 0..255; K=32 per chunk; 22 chunks) ----------
__device__ __forceinline__ void stageA(int c, int t, uint32_t abuf_u32, __half* abuf_h,
        const float* s_gi, const int* s_src, const int* s_dst,
        const float* s_dsp, const float* s_scl,
        const float* __restrict__ w_geom, const float* __restrict__ chain_freq) {
    const int e = t >> 2, p = t & 3;
    if (c >= 6) {                      // rep copy: cols 192..703
        int idx = (c < 14) ? s_src[e] : s_dst[e];
        int off = (c < 14) ? (c - 6) * 32 : (c - 14) * 32;
        cpa16(abuf_u32 + e * 80 + p * 16, g_reph + idx * 256 + off + p * 8);
    } else if (c >= 4) {               // rope: cols 128..191
        float dsp = s_dsp[e], sc = s_scl[e];
        __half2 h[4];
        if (sc == 0.0f) {
            #pragma unroll
            for (int j = 0; j < 4; ++j) h[j] = __floats2half2_rn(0.0f, 0.0f);
        } else {
            #pragma unroll
            for (int j = 0; j < 4; ++j) {
                int i0 = (c - 4) * 32 + p * 8 + 2 * j, i1 = i0 + 1;
                float a0 = TWO_PI * dsp * __ldg(chain_freq + (i0 & 31));
                float a1 = TWO_PI * dsp * __ldg(chain_freq + (i1 & 31));
                float v0 = ((i0 < 32) ? sinf(a0) : cosf(a0)) * sc;
                float v1 = ((i1 < 32) ? sinf(a1) : cosf(a1)) * sc;
                h[j] = __floats2half2_rn(v0, v1);
            }
        }
        *(uint4*)(abuf_h + e * 40 + p * 8) = *(uint4*)h;
    } else {                           // geom: cols 0..127
        const float* gi = s_gi + e * 28;
        float a8[8];
        #pragma unroll
        for (int j = 0; j < 8; ++j) a8[j] = 0.0f;
        const float* wg0 = w_geom + c * 32 + p * 8;
        #pragma unroll
        for (int k = 0; k < 27; ++k) {
            float g = gi[k];
            const float4* wg = (const float4*)(wg0 + k * 128);
            float4 w0 = wg[0], w1 = wg[1];
            a8[0]+=g*w0.x; a8[1]+=g*w0.y; a8[2]+=g*w0.z; a8[3]+=g*w0.w;
            a8[4]+=g*w1.x; a8[5]+=g*w1.y; a8[6]+=g*w1.z; a8[7]+=g*w1.w;
        }
        __half2 h[4];
        #pragma unroll
        for (int j = 0; j < 4; ++j) h[j] = __floats2half2_rn(a8[2*j], a8[2*j+1]);
        *(uint4*)(abuf_h + e * 40 + p * 8) = *(uint4*)h;
    }
}

// ---------- fused edge kernel: 512 threads, 16 warps (2m x 8n) ----------
__global__ void __launch_bounds__(512, 1)
edge_kernel(const float* __restrict__ w_geom, const float* __restrict__ chain_freq,
            const float* __restrict__ b1e, const float* __restrict__ b2e,
            const int* __restrict__ ri, const int* __restrict__ cid,
            const int* __restrict__ gA, const int* __restrict__ gB,
            const int* __restrict__ pid, float* __restrict__ out) {
    extern __shared__ char smem[];
    const uint32_t sb = smem_u32(smem);
    const int t = threadIdx.x, wid = t >> 5, lane = t & 31;
    const int wm = wid & 1, wn = wid >> 1;     // wm 0..1, wn 0..7
    const int m0 = wm * 32;
    const int tb = t - 256;                    // B-loader index (threads 256..511)

    float* s_gi  = (float*)(smem + SO_GI);
    int*   s_src = (int*)(smem + SO_META);
    int*   s_dst = s_src + 64;
    float* s_dsp = (float*)(s_dst + 64);
    float* s_scl = s_dsp + 64;
    float* s_b1  = (float*)(smem + SO_B1);
    float* s_b2  = (float*)(smem + SO_B2);
    __half* s_hid = (__half*)(smem + SO_HID);

    // threads 256..511: immediately prefetch B1 chunk 0
    if (t >= 256) {
        int r = tb >> 3;
        #pragma unroll
        for (int q = 0; q < 4; ++q) {
            int s = (tb & 7) * 4 + q;
            cpa16(sb + SO_B + r * 528 + s * 16, g_w1h + r * 256 + s * 8);
        }
    }
    CP_COMMIT();

    if (t < 256) s_b1[t] = b1e[t];
    else if (tb < 128) s_b2[tb] = b2e[tb];

    if (t < EPB) {
        int e = blockIdx.x * EPB + t, src, dst;
        if (e < E_AB_LO) { src = gA[e]; dst = gB[e]; }
        else {
            int r = e - E_AB_LO, bb = r >> 10, w = r & 1023;
            src = pid[bb * 32 + (w >> 5)];
            dst = pid[bb * 32 + (w & 31)];
        }
        s_src[t] = src; s_dst[t] = dst;
        float disp = (float)(ri[src] - ri[dst]) * 0.125f;
        s_dsp[t] = disp;
        s_scl[t] = ((cid[src] == cid[dst]) ? 1.0f : 0.0f) / (fabsf(disp) + 1.0f);
        float Rs[9], Rd[9];
        #pragma unroll
        for (int i = 0; i < 9; ++i) { Rs[i] = g_R[src*9+i]; Rd[i] = g_R[dst*9+i]; }
        float dx = g_t[dst*3+0]-g_t[src*3+0], dy = g_t[dst*3+1]-g_t[src*3+1], dz = g_t[dst*3+2]-g_t[src*3+2];
        float dist = sqrtf(dx*dx + dy*dy + dz*dz + EPSF);
        float* gi = s_gi + t * 28;
        #pragma unroll
        for (int i = 0; i < NB; ++i) {
            float z = (dist - (20.0f/14.0f)*(float)i) * 0.75f;
            gi[i] = expf(-0.5f * z * z);
        }
        #pragma unroll
        for (int a = 0; a < 3; ++a)
            #pragma unroll
            for (int b = 0; b < 3; ++b)
                gi[15 + a*3 + b] = Rs[a]*Rd[b] + Rs[3+a]*Rd[3+b] + Rs[6+a]*Rd[6+b];
        float inv = 1.0f / (dist + 1.0f);
        #pragma unroll
        for (int k = 0; k < 3; ++k)
            gi[24 + k] = (Rs[k]*dx + Rs[3+k]*dy + Rs[6+k]*dz) * inv;
    }
    __syncthreads();

    // stage A chunk 0 (geom, computed by threads 0..255)
    if (t < 256)
        stageA(0, t, sb + SO_A, (__half*)(smem + SO_A), s_gi, s_src, s_dst, s_dsp, s_scl, w_geom, chain_freq);
    CP_COMMIT();
    CP_WAIT0();
    __syncthreads();

    // ---- GEMM1: 22 chunks of K=32; warp tile 32m x 32n ----
    float acc[2][4][4];
    #pragma unroll
    for (int s = 0; s < 2; ++s)
        #pragma unroll
        for (int n = 0; n < 4; ++n)
            #pragma unroll
            for (int q = 0; q < 4; ++q) acc[s][n][q] = 0.0f;

    for (int c = 0; c < 22; ++c) {
        const int nb = (c + 1) & 1;
        if (t < 256) {
            if (c < 21)
                stageA(c + 1, t, sb + SO_A + nb * 5120, (__half*)(smem + SO_A + nb * 5120),
                       s_gi, s_src, s_dst, s_dsp, s_scl, w_geom, chain_freq);
        } else {
            if (c < 21) {
                int r = tb >> 3;
                #pragma unroll
                for (int q = 0; q < 4; ++q) {
                    int s = (tb & 7) * 4 + q;
                    cpa16(sb + SO_B + nb * 16896 + r * 528 + s * 16,
                          g_w1h + ((c + 1) * 32 + r) * 256 + s * 8);
                }
            } else {
                // prefetch B2 chunk 0 into buf 0
                int r = tb >> 3;
                #pragma unroll
                for (int q = 0; q < 2; ++q) {
                    int s = (tb & 7) * 2 + q;
                    cpa16(sb + SO_B + r * 272 + s * 16, g_w2h + r * 128 + s * 8);
                }
            }
        }
        CP_COMMIT();

        const uint32_t Ab = sb + SO_A + (c & 1) * 5120;
        const uint32_t Bb = sb + SO_B + (c & 1) * 16896;
        #pragma unroll
        for (int ks = 0; ks < 2; ++ks) {
            uint32_t a[2][4];
            #pragma unroll
            for (int sub = 0; sub < 2; ++sub)
                ldmx4(a[sub], Ab + (uint32_t)((m0 + sub*16 + (lane & 15)) * 80 + (ks*16 + (lane >> 4) * 8) * 2));
            #pragma unroll
            for (int np = 0; np < 2; ++np) {
                uint32_t b[4];
                ldmx4t(b, Bb + (uint32_t)((ks*16 + (lane & 15)) * 528 + (wn*32 + np*16 + (lane >> 4) * 8) * 2));
                mma16816(acc[0][np*2],   a[0], b[0], b[1]);
                mma16816(acc[0][np*2+1], a[0], b[2], b[3]);
                mma16816(acc[1][np*2],   a[1], b[0], b[1]);
                mma16816(acc[1][np*2+1], a[1], b[2], b[3]);
            }
        }
        CP_WAIT0();
        __syncthreads();
    }

    // ---- epilogue 1: bias + gelu -> s_hid; prefetch B2 chunk 1 ----
    {
        if (t >= 256) {
            int r = tb >> 3;
            #pragma unroll
            for (int q = 0; q < 2; ++q) {
                int s = (tb & 7) * 2 + q;
                cpa16(sb + SO_B + 16896 + r * 272 + s * 16, g_w2h + (32 + r) * 128 + s * 8);
            }
        }
        CP_COMMIT();
        const int r0 = m0 + (lane >> 2);
        const int cb = wn * 32 + (lane & 3) * 2;
        #pragma unroll
        for (int sub = 0; sub < 2; ++sub) {
            int rA = r0 + sub * 16;
            #pragma unroll
            for (int nt = 0; nt < 4; ++nt) {
                int col = cb + nt * 8;
                float bb0 = s_b1[col], bb1 = s_b1[col + 1];
                float* A = acc[sub][nt];
                *(__half2*)(s_hid + rA * 264 + col) =
                    __floats2half2_rn(gelu_tanh(A[0] + bb0), gelu_tanh(A[1] + bb1));
                *(__half2*)(s_hid + (rA + 8) * 264 + col) =
                    __floats2half2_rn(gelu_tanh(A[2] + bb0), gelu_tanh(A[3] + bb1));
            }
        }
        CP_WAIT0();
        __syncthreads();
    }

    // ---- GEMM2: 8 chunks of K=32; warp tile 32m x 16n ----
    float acc2[2][2][4];
    #pragma unroll
    for (int s = 0; s < 2; ++s)
        #pragma unroll
        for (int n = 0; n < 2; ++n)
            #pragma unroll
            for (int q = 0; q < 4; ++q) acc2[s][n][q] = 0.0f;

    for (int d = 0; d < 8; ++d) {
        if (t >= 256 && d >= 1 && d < 7) {
            int nb = (d + 1) & 1;
            int r = tb >> 3;
            #pragma unroll
            for (int q = 0; q < 2; ++q) {
                int s = (tb & 7) * 2 + q;
                cpa16(sb + SO_B + nb * 16896 + r * 272 + s * 16,
                      g_w2h + ((d + 1) * 32 + r) * 128 + s * 8);
            }
        }
        CP_COMMIT();
        const uint32_t Bb = sb + SO_B + (d & 1) * 16896;
        #pragma unroll
        for (int ks = 0; ks < 2; ++ks) {
            uint32_t a[2][4];
            #pragma unroll
            for (int sub = 0; sub < 2; ++sub)
                ldmx4(a[sub], sb + SO_HID +
                    (uint32_t)(((m0 + sub*16 + (lane & 15)) * 264 + d*32 + ks*16 + (lane >> 4) * 8) * 2));
            uint32_t b[4];
            ldmx4t(b, Bb + (uint32_t)((ks*16 + (lane & 15)) * 272 + (wn*16 + (lane >> 4) * 8) * 2));
            mma16816(acc2[0][0], a[0], b[0], b[1]);
            mma16816(acc2[0][1], a[0], b[2], b[3]);
            mma16816(acc2[1][0], a[1], b[0], b[1]);
            mma16816(acc2[1][1], a[1], b[2], b[3]);
        }
        CP_WAIT0();
        __syncthreads();
    }

    // ---- epilogue 2: bias + store ----
    {
        const int r0 = m0 + (lane >> 2);
        const int cb = wn * 16 + (lane & 3) * 2;
        #pragma unroll
        for (int sub = 0; sub < 2; ++sub) {
            int rA = r0 + sub * 16;
            int eg0 = blockIdx.x * EPB + rA;
            #pragma unroll
            for (int nt = 0; nt < 2; ++nt) {
                int col = cb + nt * 8;
                float bb0 = s_b2[col], bb1 = s_b2[col + 1];
                float* A = acc2[sub][nt];
                *(float2*)(out + eg0 * 128 + col)       = make_float2(A[0] + bb0, A[1] + bb1);
                *(float2*)(out + (eg0 + 8) * 128 + col) = make_float2(A[2] + bb0, A[3] + bb1);
            }
        }
    }
}

// ---------- launch ----------
extern "C" void kernel_launch(void* const* d_in, const int* in_sizes, int n_in,
                              void* d_out, int out_size) {
    const float* emb        = (const float*)d_in[0];
    const float* ts         = (const float*)d_in[1];
    const float* coords     = (const float*)d_in[2];
    const float* time_freq  = (const float*)d_in[3];
    const float* chain_freq = (const float*)d_in[4];
    const float* w1_res     = (const float*)d_in[5];
    const float* b1_res     = (const float*)d_in[6];
    const float* w2_res     = (const float*)d_in[7];
    const float* b2_res     = (const float*)d_in[8];
    const float* w_geom     = (const float*)d_in[9];
    const float* w1_edge    = (const float*)d_in[10];
    const float* b1_edge    = (const float*)d_in[11];
    const float* w2_edge    = (const float*)d_in[12];
    const float* b2_edge    = (const float*)d_in[13];
    const int*   ri         = (const int*)d_in[14];
    const int*   cid        = (const int*)d_in[15];
    const int*   gA         = (const int*)d_in[16];
    const int*   gB         = (const int*)d_in[17];
    const int*   pid        = (const int*)d_in[18];
    float* out = (float*)d_out;

    cudaFuncSetAttribute(edge_kernel, cudaFuncAttributeMaxDynamicSharedMemorySize, SMEM_EDGE);

    prep_kernel<<<1088, 256>>>(emb, ts, time_freq, w1_res, b1_res, w2_res, b2_res,
                               coords, w1_edge, w2_edge);
    edge_kernel<<<EDGE_BLOCKS, 512, SMEM_EDGE>>>(
        w_geom, chain_freq, b1_edge, b2_edge, ri, cid, gA, gB, pid, out);
}

// round 7
// speedup vs baseline: 7.4009x; 1.4371x over previous
#include <cuda_runtime.h>
#include <cuda_fp16.h>
#include <cstdint>
#include <math.h>

#define N_RES   1024
#define NB      15
#define E_AB_LO 131072
#define E_TOT   133120
#define EPSF    1e-6f
#define TWO_PI  6.283185307179586f

#define EPB     128
#define EDGE_BLOCKS (E_TOT / EPB)     // 1040

// smem byte offsets (edge kernel)
#define SO_A    0                     // 2 x 128x40 half = 20480
#define SO_B    20480                 // 2 x 16896 = 33792
#define SO_HID  54272                 // 128 x 264 half = 67584
#define SO_GI   121856                // 128*28*4 = 14336
#define SO_META 136192                // 2048
#define SO_B1   138240                // 1024
#define SO_B2   139264                // 512
#define SMEM_EDGE 139776

__device__ __half g_reph[N_RES * 256];
__device__ float  g_R[N_RES * 9];
__device__ float  g_t[N_RES * 3];
__device__ __half g_w1h[704 * 256];
__device__ __half g_w2h[256 * 128];

// ---------- helpers ----------
__device__ __forceinline__ uint32_t smem_u32(const void* p) {
    uint32_t a;
    asm("{ .reg .u64 t; cvta.to.shared.u64 t, %1; cvt.u32.u64 %0, t; }" : "=r"(a) : "l"(p));
    return a;
}
__device__ __forceinline__ void ldmx4(uint32_t* r, uint32_t addr) {
    asm volatile("ldmatrix.sync.aligned.m8n8.x4.shared.b16 {%0,%1,%2,%3}, [%4];"
        : "=r"(r[0]), "=r"(r[1]), "=r"(r[2]), "=r"(r[3]) : "r"(addr));
}
__device__ __forceinline__ void ldmx4t(uint32_t* r, uint32_t addr) {
    asm volatile("ldmatrix.sync.aligned.m8n8.x4.trans.shared.b16 {%0,%1,%2,%3}, [%4];"
        : "=r"(r[0]), "=r"(r[1]), "=r"(r[2]), "=r"(r[3]) : "r"(addr));
}
__device__ __forceinline__ void mma16816(float* d, const uint32_t* a, uint32_t b0, uint32_t b1) {
    asm volatile("mma.sync.aligned.m16n8k16.row.col.f32.f16.f16.f32 "
        "{%0,%1,%2,%3},{%4,%5,%6,%7},{%8,%9},{%0,%1,%2,%3};"
        : "+f"(d[0]), "+f"(d[1]), "+f"(d[2]), "+f"(d[3])
        : "r"(a[0]), "r"(a[1]), "r"(a[2]), "r"(a[3]), "r"(b0), "r"(b1));
}
__device__ __forceinline__ void cpa16(uint32_t dst, const void* src) {
    asm volatile("cp.async.cg.shared.global [%0], [%1], 16;" :: "r"(dst), "l"(src));
}
#define CP_COMMIT() asm volatile("cp.async.commit_group;" ::: "memory")
#define CP_WAIT0()  asm volatile("cp.async.wait_group 0;" ::: "memory")

__device__ __forceinline__ float gelu_tanh(float x) {
    float x3 = x * x * x;
    return 0.5f * x * (1.0f + tanhf(0.7978845608028654f * (x + 0.044715f * x3)));
}

// ---------- prep kernel: residue MLP (blocks 0..255) + aux (blocks 256..1087) ----------
__global__ void __launch_bounds__(256) prep_kernel(
        const float* __restrict__ emb, const float* __restrict__ ts,
        const float* __restrict__ tf,  const float* __restrict__ w1,
        const float* __restrict__ b1,  const float* __restrict__ w2,
        const float* __restrict__ b2,
        const float* __restrict__ coords,
        const float* __restrict__ w1e, const float* __restrict__ w2e) {
    const int t = threadIdx.x;
    if (blockIdx.x >= 256) {
        int g = (blockIdx.x - 256) * 256 + t;
        if (g < 704 * 256) g_w1h[g] = __float2half(w1e[g]);
        else               g_w2h[g - 704 * 256] = __float2half(w2e[g - 704 * 256]);
        if (g < N_RES) {
            const float* c = coords + g * 9;
            float ax=c[0],ay=c[1],az=c[2], bx=c[3],by=c[4],bz=c[5], cx=c[6],cy=c[7],cz=c[8];
            float v1x=cx-bx,v1y=cy-by,v1z=cz-bz, v2x=ax-bx,v2y=ay-by,v2z=az-bz;
            float n1 = sqrtf(v1x*v1x+v1y*v1y+v1z*v1z) + EPSF;
            float e1x=v1x/n1,e1y=v1y/n1,e1z=v1z/n1;
            float dp = e1x*v2x+e1y*v2y+e1z*v2z;
            float u2x=v2x-e1x*dp,u2y=v2y-e1y*dp,u2z=v2z-e1z*dp;
            float n2 = sqrtf(u2x*u2x+u2y*u2y+u2z*u2z) + EPSF;
            float e2x=u2x/n2,e2y=u2y/n2,e2z=u2z/n2;
            float e3x=e1y*e2z-e1z*e2y, e3y=e1z*e2x-e1x*e2z, e3z=e1x*e2y-e1y*e2x;
            float* R = g_R + g * 9;
            R[0]=e1x;R[1]=e2x;R[2]=e3x; R[3]=e1y;R[4]=e2y;R[5]=e3y; R[6]=e1z;R[7]=e2z;R[8]=e3z;
            g_t[g*3+0]=bx; g_t[g*3+1]=by; g_t[g*3+2]=bz;
        }
        return;
    }
    __shared__ float sx[4 * 288];
    __shared__ float sh[4 * 256];
    const int r0 = blockIdx.x * 4;
    #pragma unroll
    for (int i = 0; i < 5; ++i) {
        int idx = t + i * 256;
        if (idx < 4 * 288) {
            int row = idx / 288, col = idx - row * 288;
            float v;
            if (col < 256) v = emb[(r0 + row) * 256 + col];
            else {
                int cc = col - 256;
                float ang = TWO_PI * ts[r0 + row] * tf[cc & 15];
                v = (cc < 16) ? sinf(ang) : cosf(ang);
            }
            sx[idx] = v;
        }
    }
    __syncthreads();
    float acc[4] = {0.f, 0.f, 0.f, 0.f};
    #pragma unroll 8
    for (int k = 0; k < 288; ++k) {
        float w = __ldg(w1 + k * 256 + t);
        acc[0] += sx[k]       * w;
        acc[1] += sx[288 + k] * w;
        acc[2] += sx[576 + k] * w;
        acc[3] += sx[864 + k] * w;
    }
    float bb = b1[t];
    #pragma unroll
    for (int r = 0; r < 4; ++r) sh[r * 256 + t] = gelu_tanh(acc[r] + bb);
    __syncthreads();
    float ac2[4] = {0.f, 0.f, 0.f, 0.f};
    #pragma unroll 8
    for (int k = 0; k < 256; ++k) {
        float w = __ldg(w2 + k * 256 + t);
        ac2[0] += sh[k]       * w;
        ac2[1] += sh[256 + k] * w;
        ac2[2] += sh[512 + k] * w;
        ac2[3] += sh[768 + k] * w;
    }
    float bb2 = b2[t];
    #pragma unroll
    for (int r = 0; r < 4; ++r)
        g_reph[(r0 + r) * 256 + t] = __float2half(ac2[r] + bb2 + sx[r * 288 + t]);
}

// ---------- A chunk staging (all 512 threads; 128 edges x K=32) ----------
__device__ __forceinline__ void stageA(int c, int t, uint32_t abuf_u32, __half* abuf_h,
        const float* s_gi, const int* s_src, const int* s_dst,
        const float* s_dsp, const float* s_scl,
        const float* __restrict__ w_geom, const float* __restrict__ chain_freq) {
    const int e = t >> 2, p = t & 3;
    if (c >= 6) {                      // rep copy: cols 192..703
        int idx = (c < 14) ? s_src[e] : s_dst[e];
        int off = (c < 14) ? (c - 6) * 32 : (c - 14) * 32;
        cpa16(abuf_u32 + e * 80 + p * 16, g_reph + idx * 256 + off + p * 8);
    } else if (c >= 4) {               // rope: cols 128..191
        float dsp = s_dsp[e], sc = s_scl[e];
        __half2 h[4];
        if (sc == 0.0f) {
            #pragma unroll
            for (int j = 0; j < 4; ++j) h[j] = __floats2half2_rn(0.0f, 0.0f);
        } else {
            #pragma unroll
            for (int j = 0; j < 4; ++j) {
                int i0 = (c - 4) * 32 + p * 8 + 2 * j, i1 = i0 + 1;
                float a0 = TWO_PI * dsp * __ldg(chain_freq + (i0 & 31));
                float a1 = TWO_PI * dsp * __ldg(chain_freq + (i1 & 31));
                float v0 = ((i0 < 32) ? sinf(a0) : cosf(a0)) * sc;
                float v1 = ((i1 < 32) ? sinf(a1) : cosf(a1)) * sc;
                h[j] = __floats2half2_rn(v0, v1);
            }
        }
        *(uint4*)(abuf_h + e * 40 + p * 8) = *(uint4*)h;
    } else {                           // geom: cols 0..127
        const float* gi = s_gi + e * 28;
        float a8[8];
        #pragma unroll
        for (int j = 0; j < 8; ++j) a8[j] = 0.0f;
        const float* wg0 = w_geom + c * 32 + p * 8;
        #pragma unroll
        for (int k = 0; k < 27; ++k) {
            float g = gi[k];
            const float4* wg = (const float4*)(wg0 + k * 128);
            float4 w0 = wg[0], w1 = wg[1];
            a8[0]+=g*w0.x; a8[1]+=g*w0.y; a8[2]+=g*w0.z; a8[3]+=g*w0.w;
            a8[4]+=g*w1.x; a8[5]+=g*w1.y; a8[6]+=g*w1.z; a8[7]+=g*w1.w;
        }
        __half2 h[4];
        #pragma unroll
        for (int j = 0; j < 4; ++j) h[j] = __floats2half2_rn(a8[2*j], a8[2*j+1]);
        *(uint4*)(abuf_h + e * 40 + p * 8) = *(uint4*)h;
    }
}

// ---------- B chunk loaders (all 512 threads) ----------
__device__ __forceinline__ void loadB1(int c, int t, uint32_t bbuf) {
    int r = t >> 4;                   // 0..31
    #pragma unroll
    for (int q = 0; q < 2; ++q) {
        int s = (t & 15) * 2 + q;     // 0..31 (16B units)
        cpa16(bbuf + r * 528 + s * 16, g_w1h + (c * 32 + r) * 256 + s * 8);
    }
}
__device__ __forceinline__ void loadB2(int d, int t, uint32_t bbuf) {
    int r = t >> 4;                   // 0..31
    int s = t & 15;                   // 0..15 (16B units)
    cpa16(bbuf + r * 272 + s * 16, g_w2h + (d * 32 + r) * 128 + s * 8);
}

// ---------- fused edge kernel: 512 threads, 16 warps (4m x 4n), M=128 ----------
__global__ void __launch_bounds__(512, 1)
edge_kernel(const float* __restrict__ w_geom, const float* __restrict__ chain_freq,
            const float* __restrict__ b1e, const float* __restrict__ b2e,
            const int* __restrict__ ri, const int* __restrict__ cid,
            const int* __restrict__ gA, const int* __restrict__ gB,
            const int* __restrict__ pid, float* __restrict__ out) {
    extern __shared__ char smem[];
    const uint32_t sb = smem_u32(smem);
    const int t = threadIdx.x, wid = t >> 5, lane = t & 31;
    const int wm = wid & 3, wn = wid >> 2;     // 4m x 4n
    const int m0 = wm * 32;

    float* s_gi  = (float*)(smem + SO_GI);
    int*   s_src = (int*)(smem + SO_META);
    int*   s_dst = s_src + 128;
    float* s_dsp = (float*)(s_dst + 128);
    float* s_scl = s_dsp + 128;
    float* s_b1  = (float*)(smem + SO_B1);
    float* s_b2  = (float*)(smem + SO_B2);
    __half* s_hid = (__half*)(smem + SO_HID);

    // prefetch B1 chunk 0 immediately
    loadB1(0, t, sb + SO_B);
    CP_COMMIT();

    if (t < 256) s_b1[t] = b1e[t];
    else if (t < 384) s_b2[t - 256] = b2e[t - 256];

    if (t < EPB) {
        int e = blockIdx.x * EPB + t, src, dst;
        if (e < E_AB_LO) { src = gA[e]; dst = gB[e]; }
        else {
            int r = e - E_AB_LO, bb = r >> 10, w = r & 1023;
            src = pid[bb * 32 + (w >> 5)];
            dst = pid[bb * 32 + (w & 31)];
        }
        s_src[t] = src; s_dst[t] = dst;
        float disp = (float)(ri[src] - ri[dst]) * 0.125f;
        s_dsp[t] = disp;
        s_scl[t] = ((cid[src] == cid[dst]) ? 1.0f : 0.0f) / (fabsf(disp) + 1.0f);
        float Rs[9], Rd[9];
        #pragma unroll
        for (int i = 0; i < 9; ++i) { Rs[i] = g_R[src*9+i]; Rd[i] = g_R[dst*9+i]; }
        float dx = g_t[dst*3+0]-g_t[src*3+0], dy = g_t[dst*3+1]-g_t[src*3+1], dz = g_t[dst*3+2]-g_t[src*3+2];
        float dist = sqrtf(dx*dx + dy*dy + dz*dz + EPSF);
        float* gi = s_gi + t * 28;
        #pragma unroll
        for (int i = 0; i < NB; ++i) {
            float z = (dist - (20.0f/14.0f)*(float)i) * 0.75f;
            gi[i] = expf(-0.5f * z * z);
        }
        #pragma unroll
        for (int a = 0; a < 3; ++a)
            #pragma unroll
            for (int b = 0; b < 3; ++b)
                gi[15 + a*3 + b] = Rs[a]*Rd[b] + Rs[3+a]*Rd[3+b] + Rs[6+a]*Rd[6+b];
        float inv = 1.0f / (dist + 1.0f);
        #pragma unroll
        for (int k = 0; k < 3; ++k)
            gi[24 + k] = (Rs[k]*dx + Rs[3+k]*dy + Rs[6+k]*dz) * inv;
    }
    __syncthreads();

    // stage A chunk 0 (geom)
    stageA(0, t, sb + SO_A, (__half*)(smem + SO_A), s_gi, s_src, s_dst, s_dsp, s_scl, w_geom, chain_freq);
    CP_COMMIT();
    CP_WAIT0();
    __syncthreads();

    // ---- GEMM1: 22 chunks of K=32; warp tile 32m x 64n ----
    float acc[2][8][4];
    #pragma unroll
    for (int s = 0; s < 2; ++s)
        #pragma unroll
        for (int n = 0; n < 8; ++n)
            #pragma unroll
            for (int q = 0; q < 4; ++q) acc[s][n][q] = 0.0f;

    for (int c = 0; c < 22; ++c) {
        const int nb = (c + 1) & 1;
        if (c < 21) {
            loadB1(c + 1, t, sb + SO_B + nb * 16896);
            stageA(c + 1, t, sb + SO_A + nb * 10240, (__half*)(smem + SO_A + nb * 10240),
                   s_gi, s_src, s_dst, s_dsp, s_scl, w_geom, chain_freq);
        } else {
            loadB2(0, t, sb + SO_B);   // B2 chunk 0 into buf 0
        }
        CP_COMMIT();

        const uint32_t Ab = sb + SO_A + (c & 1) * 10240;
        const uint32_t Bb = sb + SO_B + (c & 1) * 16896;
        #pragma unroll
        for (int ks = 0; ks < 2; ++ks) {
            uint32_t a[2][4];
            #pragma unroll
            for (int sub = 0; sub < 2; ++sub)
                ldmx4(a[sub], Ab + (uint32_t)((m0 + sub*16 + (lane & 15)) * 80 + (ks*16 + (lane >> 4) * 8) * 2));
            #pragma unroll
            for (int np = 0; np < 4; ++np) {
                uint32_t b[4];
                ldmx4t(b, Bb + (uint32_t)((ks*16 + (lane & 15)) * 528 + (wn*64 + np*16 + (lane >> 4) * 8) * 2));
                mma16816(acc[0][np*2],   a[0], b[0], b[1]);
                mma16816(acc[0][np*2+1], a[0], b[2], b[3]);
                mma16816(acc[1][np*2],   a[1], b[0], b[1]);
                mma16816(acc[1][np*2+1], a[1], b[2], b[3]);
            }
        }
        CP_WAIT0();
        __syncthreads();
    }

    // ---- epilogue 1: bias + gelu -> s_hid; prefetch B2 chunk 1 ----
    {
        loadB2(1, t, sb + SO_B + 16896);
        CP_COMMIT();
        const int r0 = m0 + (lane >> 2);
        const int cb = wn * 64 + (lane & 3) * 2;
        #pragma unroll
        for (int sub = 0; sub < 2; ++sub) {
            int rA = r0 + sub * 16;
            #pragma unroll
            for (int nt = 0; nt < 8; ++nt) {
                int col = cb + nt * 8;
                float bb0 = s_b1[col], bb1 = s_b1[col + 1];
                float* A = acc[sub][nt];
                *(__half2*)(s_hid + rA * 264 + col) =
                    __floats2half2_rn(gelu_tanh(A[0] + bb0), gelu_tanh(A[1] + bb1));
                *(__half2*)(s_hid + (rA + 8) * 264 + col) =
                    __floats2half2_rn(gelu_tanh(A[2] + bb0), gelu_tanh(A[3] + bb1));
            }
        }
        CP_WAIT0();
        __syncthreads();
    }

    // ---- GEMM2: 8 chunks of K=32; warp tile 32m x 32n ----
    float acc2[2][4][4];
    #pragma unroll
    for (int s = 0; s < 2; ++s)
        #pragma unroll
        for (int n = 0; n < 4; ++n)
            #pragma unroll
            for (int q = 0; q < 4; ++q) acc2[s][n][q] = 0.0f;

    for (int d = 0; d < 8; ++d) {
        if (d >= 1 && d < 7) {
            loadB2(d + 1, t, sb + SO_B + ((d + 1) & 1) * 16896);
        }
        CP_COMMIT();
        const uint32_t Bb = sb + SO_B + (d & 1) * 16896;
        #pragma unroll
        for (int ks = 0; ks < 2; ++ks) {
            uint32_t a[2][4];
            #pragma unroll
            for (int sub = 0; sub < 2; ++sub)
                ldmx4(a[sub], sb + SO_HID +
                    (uint32_t)(((m0 + sub*16 + (lane & 15)) * 264 + d*32 + ks*16 + (lane >> 4) * 8) * 2));
            #pragma unroll
            for (int np = 0; np < 2; ++np) {
                uint32_t b[4];
                ldmx4t(b, Bb + (uint32_t)((ks*16 + (lane & 15)) * 272 + (wn*32 + np*16 + (lane >> 4) * 8) * 2));
                mma16816(acc2[0][np*2],   a[0], b[0], b[1]);
                mma16816(acc2[0][np*2+1], a[0], b[2], b[3]);
                mma16816(acc2[1][np*2],   a[1], b[0], b[1]);
                mma16816(acc2[1][np*2+1], a[1], b[2], b[3]);
            }
        }
        CP_WAIT0();
        __syncthreads();
    }

    // ---- epilogue 2: bias + store ----
    {
        const int r0 = m0 + (lane >> 2);
        const int cb = wn * 32 + (lane & 3) * 2;
        #pragma unroll
        for (int sub = 0; sub < 2; ++sub) {
            int rA = r0 + sub * 16;
            int eg0 = blockIdx.x * EPB + rA;
            #pragma unroll
            for (int nt = 0; nt < 4; ++nt) {
                int col = cb + nt * 8;
                float bb0 = s_b2[col], bb1 = s_b2[col + 1];
                float* A = acc2[sub][nt];
                *(float2*)(out + eg0 * 128 + col)       = make_float2(A[0] + bb0, A[1] + bb1);
                *(float2*)(out + (eg0 + 8) * 128 + col) = make_float2(A[2] + bb0, A[3] + bb1);
            }
        }
    }
}

// ---------- launch ----------
extern "C" void kernel_launch(void* const* d_in, const int* in_sizes, int n_in,
                              void* d_out, int out_size) {
    const float* emb        = (const float*)d_in[0];
    const float* ts         = (const float*)d_in[1];
    const float* coords     = (const float*)d_in[2];
    const float* time_freq  = (const float*)d_in[3];
    const float* chain_freq = (const float*)d_in[4];
    const float* w1_res     = (const float*)d_in[5];
    const float* b1_res     = (const float*)d_in[6];
    const float* w2_res     = (const float*)d_in[7];
    const float* b2_res     = (const float*)d_in[8];
    const float* w_geom     = (const float*)d_in[9];
    const float* w1_edge    = (const float*)d_in[10];
    const float* b1_edge    = (const float*)d_in[11];
    const float* w2_edge    = (const float*)d_in[12];
    const float* b2_edge    = (const float*)d_in[13];
    const int*   ri         = (const int*)d_in[14];
    const int*   cid        = (const int*)d_in[15];
    const int*   gA         = (const int*)d_in[16];
    const int*   gB         = (const int*)d_in[17];
    const int*   pid        = (const int*)d_in[18];
    float* out = (float*)d_out;

    cudaFuncSetAttribute(edge_kernel, cudaFuncAttributeMaxDynamicSharedMemorySize, SMEM_EDGE);

    prep_kernel<<<1088, 256>>>(emb, ts, time_freq, w1_res, b1_res, w2_res, b2_res,
                               coords, w1_edge, w2_edge);
    edge_kernel<<<EDGE_BLOCKS, 512, SMEM_EDGE>>>(
        w_geom, chain_freq, b1_edge, b2_edge, ri, cid, gA, gB, pid, out);
}